// round 11
// baseline (speedup 1.0000x reference)
#include <cuda_runtime.h>
#include <cuda_bf16.h>
#include <cstdint>

#define LSEQ 128
#define DDIM 768
#define NBATCH 8
#define ROWS (NBATCH * LSEQ)   // 1024

// ---------------- scratch (__device__ globals; no allocation) ----------------
__device__ float g_hi[ROWS * DDIM];      // hi (fp32)
__device__ float g_a[NBATCH * LSEQ * LSEQ];
__device__ float g_denom[ROWS];
__device__ float g_y[ROWS * DDIM];
__device__ float g_buf[2][ROWS * DDIM];
__device__ __align__(16) __nv_bfloat16 g_hj2[ROWS * DDIM];  // hj bf16 (direct from GEMM)
__device__ __align__(16) __nv_bfloat16 g_tH[ROWS * DDIM];   // t split hi
__device__ __align__(16) __nv_bfloat16 g_tL[ROWS * DDIM];   // t split lo
// w2 fragments (m16n8k16 B order): [nn 0..47][kk 0..47][lane]
__device__ __align__(16) uint2 g_bfrag[48 * 48 * 32];
// gw split-bf16 fragments: [li*96 + nn][kk 0..47][lane]
__device__ __align__(16) uint2 g_gwfH[3 * 96 * 48 * 32];
__device__ __align__(16) uint2 g_gwfL[3 * 96 * 48 * 32];

// ============================================================================
// PTX helpers (baseline features only)
// ============================================================================
__device__ __forceinline__ uint32_t smem_to_u32(const void* p) {
    uint32_t a;
    asm("{ .reg .u64 t; cvta.to.shared.u64 t, %1; cvt.u32.u64 %0, t; }" : "=r"(a) : "l"(p));
    return a;
}
#define CP_ASYNC16(dst, src) \
    asm volatile("cp.async.cg.shared.global [%0], [%1], 16;" :: "r"(dst), "l"(src))
#define CP_COMMIT() asm volatile("cp.async.commit_group;" ::: "memory")
#define CP_WAIT0()  asm volatile("cp.async.wait_group 0;" ::: "memory")

__device__ __forceinline__ void ldsm_x4(uint32_t& r0, uint32_t& r1, uint32_t& r2,
                                        uint32_t& r3, uint32_t addr) {
    asm volatile("ldmatrix.sync.aligned.m8n8.x4.shared.b16 {%0,%1,%2,%3}, [%4];"
                 : "=r"(r0), "=r"(r1), "=r"(r2), "=r"(r3) : "r"(addr));
}
__device__ __forceinline__ void mma_bf16(float* c, const uint32_t* a, const uint32_t* b) {
    asm volatile("mma.sync.aligned.m16n8k16.row.col.f32.bf16.bf16.f32 "
                 "{%0,%1,%2,%3}, {%4,%5,%6,%7}, {%8,%9}, {%0,%1,%2,%3};"
                 : "+f"(c[0]), "+f"(c[1]), "+f"(c[2]), "+f"(c[3])
                 : "r"(a[0]), "r"(a[1]), "r"(a[2]), "r"(a[3]), "r"(b[0]), "r"(b[1]));
}
__device__ __forceinline__ void mma_tf32(float* c, const uint32_t* a, const uint32_t* b) {
    asm volatile("mma.sync.aligned.m16n8k8.row.col.f32.tf32.tf32.f32 "
                 "{%0,%1,%2,%3}, {%4,%5,%6,%7}, {%8,%9}, {%0,%1,%2,%3};"
                 : "+f"(c[0]), "+f"(c[1]), "+f"(c[2]), "+f"(c[3])
                 : "r"(a[0]), "r"(a[1]), "r"(a[2]), "r"(a[3]), "r"(b[0]), "r"(b[1]));
}
__device__ __forceinline__ uint32_t f2tf32(float x) {
    uint32_t r;
    asm("cvt.rna.tf32.f32 %0, %1;" : "=r"(r) : "f"(x));
    return r;
}
__device__ __forceinline__ void f2tf32x2(float x, uint32_t& hi, uint32_t& lo) {
    hi = f2tf32(x);
    lo = f2tf32(x - __uint_as_float(hi));
}
__device__ __forceinline__ uint32_t pack_bf16x2(float a, float b) {
    __nv_bfloat162 r = __floats2bfloat162_rn(a, b);
    return *(uint32_t*)&r;
}
// bf16x2: max(a + b, 0)
__device__ __forceinline__ uint32_t hadd_relu2(uint32_t a, uint32_t b) {
    __nv_bfloat162 z = __floats2bfloat162_rn(0.f, 0.f);
    __nv_bfloat162 r = __hmax2(__hadd2(*(__nv_bfloat162*)&a, *(__nv_bfloat162*)&b), z);
    return *(uint32_t*)&r;
}

// ============================================================================
// tf32 tensor GEMM: row-major. BM x 64 x BK=16 tiles.
// BM=128: 8 warps 4Mx2N. BM=64: 8 warps 2Mx4N.
// EXACT: 3xTF32. OMODE: 0 = fp32 C (+Cadd), 1 = bf16 hi/lo split, 2 = bf16.
// ============================================================================
#define TAP 20
#define TBP 72

template <int BM, bool EXACT, int OMODE>
__global__ __launch_bounds__(256)
void gemm_tf32(const float* __restrict__ A, const float* __restrict__ B,
               float* __restrict__ C, const float* __restrict__ Cadd,
               __nv_bfloat16* __restrict__ outH, __nv_bfloat16* __restrict__ outL,
               int M, int N, int K, long sA, long sB, long sC)
{
    constexpr int WN = (BM == 128) ? 2 : 4;
    constexpr int NT = (BM == 128) ? 4 : 2;

    const int bz = blockIdx.z;
    A += (long)bz * sA;
    B += (long)bz * sB;
    const long coff = (long)bz * sC;

    const int bm = blockIdx.y * BM;
    const int bn = blockIdx.x * 64;

    __shared__ float As[2][BM][TAP];
    __shared__ float Bs[2][16][TBP];

    const int tid  = threadIdx.x;
    const int lane = tid & 31;
    const int wid  = tid >> 5;
    const int warpM = wid / WN;
    const int warpN = wid % WN;
    const int gr = lane >> 2;
    const int gc = lane & 3;

    const uint32_t sbase = smem_to_u32(&As[0][0][0]);
    const uint32_t bbase = smem_to_u32(&Bs[0][0][0]);

    const int arow = (BM == 128) ? (tid >> 1) : (tid >> 2);
    const int akq  = (BM == 128) ? ((tid & 1) * 8) : ((tid & 3) * 4);
    const int bk   = tid >> 4;
    const int bn4  = (tid & 15) * 4;

    const int nK = K >> 4;

    {
        const float* as = A + (long)(bm + arow) * K + akq;
        uint32_t ad = sbase + (arow * TAP + akq) * 4;
        CP_ASYNC16(ad, as);
        if (BM == 128) CP_ASYNC16(ad + 16, as + 4);
        const float* bs = B + (long)bk * N + bn + bn4;
        uint32_t bd = bbase + (bk * TBP + bn4) * 4;
        CP_ASYNC16(bd, bs);
        CP_COMMIT();
    }

    float c[2][NT][4];
    #pragma unroll
    for (int mt = 0; mt < 2; mt++)
        #pragma unroll
        for (int nt = 0; nt < NT; nt++)
            #pragma unroll
            for (int q = 0; q < 4; q++) c[mt][nt][q] = 0.f;

    for (int ki = 0; ki < nK; ki++) {
        CP_WAIT0();
        __syncthreads();
        const int cur = ki & 1;
        if (ki + 1 < nK) {
            const int nxt = cur ^ 1;
            const int kc = (ki + 1) * 16;
            const float* as = A + (long)(bm + arow) * K + kc + akq;
            uint32_t ad = sbase + (nxt * BM * TAP + arow * TAP + akq) * 4;
            CP_ASYNC16(ad, as);
            if (BM == 128) CP_ASYNC16(ad + 16, as + 4);
            const float* bs = B + (long)(kc + bk) * N + bn + bn4;
            uint32_t bd = bbase + (nxt * 16 * TBP + bk * TBP + bn4) * 4;
            CP_ASYNC16(bd, bs);
            CP_COMMIT();
        }

        #pragma unroll
        for (int k8 = 0; k8 < 16; k8 += 8) {
            uint32_t ah[2][4], al[2][4];
            #pragma unroll
            for (int mt = 0; mt < 2; mt++) {
                int r0 = warpM * 32 + mt * 16 + gr;
                float v0 = As[cur][r0    ][k8 + gc];
                float v1 = As[cur][r0 + 8][k8 + gc];
                float v2 = As[cur][r0    ][k8 + gc + 4];
                float v3 = As[cur][r0 + 8][k8 + gc + 4];
                if (EXACT) {
                    f2tf32x2(v0, ah[mt][0], al[mt][0]);
                    f2tf32x2(v1, ah[mt][1], al[mt][1]);
                    f2tf32x2(v2, ah[mt][2], al[mt][2]);
                    f2tf32x2(v3, ah[mt][3], al[mt][3]);
                } else {
                    ah[mt][0] = f2tf32(v0); ah[mt][1] = f2tf32(v1);
                    ah[mt][2] = f2tf32(v2); ah[mt][3] = f2tf32(v3);
                }
            }
            uint32_t bh[NT][2], bl[NT][2];
            #pragma unroll
            for (int nt = 0; nt < NT; nt++) {
                int n = warpN * (NT * 8) + nt * 8 + gr;
                float v0 = Bs[cur][k8 + gc    ][n];
                float v1 = Bs[cur][k8 + gc + 4][n];
                if (EXACT) {
                    f2tf32x2(v0, bh[nt][0], bl[nt][0]);
                    f2tf32x2(v1, bh[nt][1], bl[nt][1]);
                } else {
                    bh[nt][0] = f2tf32(v0); bh[nt][1] = f2tf32(v1);
                }
            }
            #pragma unroll
            for (int mt = 0; mt < 2; mt++)
                #pragma unroll
                for (int nt = 0; nt < NT; nt++) {
                    if (EXACT) {
                        mma_tf32(c[mt][nt], al[mt], bh[nt]);
                        mma_tf32(c[mt][nt], ah[mt], bl[nt]);
                    }
                    mma_tf32(c[mt][nt], ah[mt], bh[nt]);
                }
        }
    }

    #pragma unroll
    for (int mt = 0; mt < 2; mt++) {
        #pragma unroll
        for (int nt = 0; nt < NT; nt++) {
            int row0 = bm + warpM * 32 + mt * 16 + gr;
            int col  = bn + warpN * (NT * 8) + nt * 8 + gc * 2;
            long o0 = coff + (long)row0 * N + col;
            long o1 = coff + (long)(row0 + 8) * N + col;
            float2 v0 = make_float2(c[mt][nt][0], c[mt][nt][1]);
            float2 v1 = make_float2(c[mt][nt][2], c[mt][nt][3]);
            if (OMODE == 1) {
                float h0 = __bfloat162float(__float2bfloat16(v0.x));
                float h1 = __bfloat162float(__float2bfloat16(v0.y));
                float h2 = __bfloat162float(__float2bfloat16(v1.x));
                float h3 = __bfloat162float(__float2bfloat16(v1.y));
                ((uint32_t*)outH)[o0 >> 1] = pack_bf16x2(h0, h1);
                ((uint32_t*)outH)[o1 >> 1] = pack_bf16x2(h2, h3);
                ((uint32_t*)outL)[o0 >> 1] = pack_bf16x2(v0.x - h0, v0.y - h1);
                ((uint32_t*)outL)[o1 >> 1] = pack_bf16x2(v1.x - h2, v1.y - h3);
            } else if (OMODE == 2) {
                ((uint32_t*)outH)[o0 >> 1] = pack_bf16x2(v0.x, v0.y);
                ((uint32_t*)outH)[o1 >> 1] = pack_bf16x2(v1.x, v1.y);
            } else {
                if (Cadd) {
                    float2 w0 = *(const float2*)(Cadd + o0);
                    float2 w1 = *(const float2*)(Cadd + o1);
                    v0.x += w0.x; v0.y += w0.y;
                    v1.x += w1.x; v1.y += w1.y;
                }
                *(float2*)(C + o0) = v0;
                *(float2*)(C + o1) = v1;
            }
        }
    }
}

// ============================================================================
// split-bf16 GEMM for y = t @ gw[li]. BM=64, BN=64, BK=32; 192 CTAs.
// ============================================================================
#define TGP 80
#define TGB 5120

__global__ __launch_bounds__(256, 4)
void gemm_tgw(const __nv_bfloat16* __restrict__ tH, const __nv_bfloat16* __restrict__ tL,
              const uint2* __restrict__ gwfH, const uint2* __restrict__ gwfL,
              int li, float* __restrict__ y)
{
    __shared__ __align__(16) char smem[2 * 2 * TGB];
    const uint32_t sbase = smem_to_u32(smem);
    const int tid  = threadIdx.x;
    const int lane = tid & 31;
    const int wid  = tid >> 5;
    const int warpM = wid >> 2;
    const int warpN = wid & 3;
    const int bm = blockIdx.y * 64;
    const int bn = blockIdx.x * 64;

    const int srow = tid >> 2;
    const int spart = tid & 3;

    {
        uint32_t d = sbase + srow * TGP + spart * 16;
        CP_ASYNC16(d, tH + (long)(bm + srow) * DDIM + spart * 8);
        CP_ASYNC16(d + TGB, tL + (long)(bm + srow) * DDIM + spart * 8);
        CP_COMMIT();
    }

    float c[2][2][4];
    #pragma unroll
    for (int mt = 0; mt < 2; mt++)
        #pragma unroll
        for (int nt = 0; nt < 2; nt++)
            #pragma unroll
            for (int q = 0; q < 4; q++) c[mt][nt][q] = 0.f;

    const long nnb = (long)li * 96 + blockIdx.x * 8 + warpN * 2;

    for (int kc = 0; kc < 24; kc++) {
        CP_WAIT0();
        __syncthreads();
        const int cur = kc & 1;
        if (kc < 23) {
            const int k0 = (kc + 1) * 32;
            uint32_t d = sbase + (cur ^ 1) * 2 * TGB + srow * TGP + spart * 16;
            CP_ASYNC16(d, tH + (long)(bm + srow) * DDIM + k0 + spart * 8);
            CP_ASYNC16(d + TGB, tL + (long)(bm + srow) * DDIM + k0 + spart * 8);
            CP_COMMIT();
        }

        #pragma unroll
        for (int ks = 0; ks < 2; ks++) {
            const int kkg = kc * 2 + ks;
            uint32_t bh[2][2], bl[2][2];
            #pragma unroll
            for (int nt = 0; nt < 2; nt++) {
                uint2 v = gwfH[((nnb + nt) * 48 + kkg) * 32 + lane];
                bh[nt][0] = v.x; bh[nt][1] = v.y;
                v = gwfL[((nnb + nt) * 48 + kkg) * 32 + lane];
                bl[nt][0] = v.x; bl[nt][1] = v.y;
            }
            #pragma unroll
            for (int mt = 0; mt < 2; mt++) {
                uint32_t addr = sbase + cur * 2 * TGB +
                    (warpM * 32 + mt * 16 + (lane & 15)) * TGP +
                    (lane >> 4) * 16 + ks * 32;
                uint32_t ahf[4], alf[4];
                ldsm_x4(ahf[0], ahf[1], ahf[2], ahf[3], addr);
                ldsm_x4(alf[0], alf[1], alf[2], alf[3], addr + TGB);
                #pragma unroll
                for (int nt = 0; nt < 2; nt++) {
                    mma_bf16(c[mt][nt], ahf, bh[nt]);
                    mma_bf16(c[mt][nt], alf, bh[nt]);
                    mma_bf16(c[mt][nt], ahf, bl[nt]);
                }
            }
        }
    }

    const int gr = lane >> 2;
    const int gc = lane & 3;
    #pragma unroll
    for (int mt = 0; mt < 2; mt++)
        #pragma unroll
        for (int nt = 0; nt < 2; nt++) {
            int row0 = bm + warpM * 32 + mt * 16 + gr;
            int col  = bn + warpN * 16 + nt * 8 + gc * 2;
            *(float2*)(y + (long)row0 * DDIM + col) =
                make_float2(c[mt][nt][0], c[mt][nt][1]);
            *(float2*)(y + (long)(row0 + 8) * DDIM + col) =
                make_float2(c[mt][nt][2], c[mt][nt][3]);
        }
}

// ============================================================================
// Coalesced fragment prep (smem-staged transpose), as in R10.
// ============================================================================
template <bool SPLIT>
__global__ void prep_frag(const float* __restrict__ src, int srcN, long srcStride,
                          int nnPerZ, uint2* __restrict__ dstH, uint2* __restrict__ dstL)
{
    __shared__ float tile[16][68];
    const int tid = threadIdx.x;
    const float* S = src + (long)blockIdx.z * srcStride;

    {
        int row = tid >> 4;
        int col4 = (tid & 15) * 4;
        float4 v = *(const float4*)(S + (long)(blockIdx.y * 16 + row) * srcN
                                    + blockIdx.x * 64 + col4);
        tile[row][col4 + 0] = v.x;
        tile[row][col4 + 1] = v.y;
        tile[row][col4 + 2] = v.z;
        tile[row][col4 + 3] = v.w;
    }
    __syncthreads();

    const int nn_local = tid >> 5;
    const int lane = tid & 31;
    const int n_l = nn_local * 8 + (lane >> 2);
    const int r0 = 2 * (lane & 3);
    float g0 = tile[r0][n_l],     g1 = tile[r0 + 1][n_l];
    float g2 = tile[r0 + 8][n_l], g3 = tile[r0 + 9][n_l];

    long nnG = (long)blockIdx.z * nnPerZ + blockIdx.x * 8 + nn_local;
    long idx = (nnG * 48 + blockIdx.y) * 32 + lane;

    if (SPLIT) {
        float h0 = __bfloat162float(__float2bfloat16(g0));
        float h1 = __bfloat162float(__float2bfloat16(g1));
        float h2 = __bfloat162float(__float2bfloat16(g2));
        float h3 = __bfloat162float(__float2bfloat16(g3));
        uint2 H, L;
        H.x = pack_bf16x2(h0, h1);           H.y = pack_bf16x2(h2, h3);
        L.x = pack_bf16x2(g0 - h0, g1 - h1); L.y = pack_bf16x2(g2 - h2, g3 - h3);
        dstH[idx] = H;
        dstL[idx] = L;
    } else {
        uint2 H;
        H.x = pack_bf16x2(g0, g1);
        H.y = pack_bf16x2(g2, g3);
        dstH[idx] = H;
    }
}

// ============================================================================
// Fused edge-MLP via mma.sync bf16. One CTA/(b,i); 2 CTAs/SM.
// A-build now in native bf16x2 (HADD2/HMAX2), hib stored as bf16.
// ============================================================================
#define APITCH 144
#define ABUF   18432
#define SM_A     0
#define SM_HIB   36864                  // 768 bf16 = 1536 B
#define SM_B2    38400
#define SM_W3    39936
#define SM_SCAL  41472
#define SM_RED   41984
#define SM_TOTAL 42048

__global__ __launch_bounds__(256, 2)
void edge_mma_kernel(const float* __restrict__ hi, const __nv_bfloat16* __restrict__ hj2,
                     const float* __restrict__ adj, const float* __restrict__ b1,
                     const uint2* __restrict__ bfrag, const float* __restrict__ b2,
                     const float* __restrict__ w3, const float* __restrict__ b3p,
                     float* __restrict__ a_out, float* __restrict__ denom_out)
{
    __shared__ __align__(16) char smem[SM_TOTAL];
    const uint32_t sbase = smem_to_u32(smem);
    const int tid  = threadIdx.x;
    const int lane = tid & 31;
    const int wid  = tid >> 5;
    const int warpM = wid >> 2;
    const int warpN = wid & 3;
    const int bi = blockIdx.x;
    const int b  = bi >> 7;
    const int i  = bi & 127;

    __nv_bfloat16* hib = (__nv_bfloat16*)(smem + SM_HIB);
    float* b2s  = (float*)(smem + SM_B2);
    float* w3s  = (float*)(smem + SM_W3);
    float* scal = (float*)(smem + SM_SCAL);
    float* red  = (float*)(smem + SM_RED);

    for (int k = tid; k < DDIM; k += 256)
        hib[k] = __float2bfloat16(hi[(long)bi * DDIM + k] + b1[k]);
    for (int k = tid; k < 384; k += 256) { b2s[k] = b2[k]; w3s[k] = w3[k]; }
    if (tid < 128) scal[tid] = 0.f;
    __syncthreads();

    const int aj = tid >> 1;
    const int ahh = tid & 1;
    const __nv_bfloat16* hjrow = hj2 + ((long)b * LSEQ + aj) * DDIM + ahh * 32;
    const __nv_bfloat16* hibp = hib + ahh * 32;
    char* abase_th = smem + SM_A + aj * APITCH + ahh * 64;

    for (int nc = 0; nc < 3; nc++) {
        float c[4][4][4];
        #pragma unroll
        for (int mt = 0; mt < 4; mt++)
            #pragma unroll
            for (int nt = 0; nt < 4; nt++)
                #pragma unroll
                for (int q = 0; q < 4; q++) c[mt][nt][q] = 0.f;

        const uint2* bb = bfrag + ((long)(nc * 16 + warpN * 4) * 48) * 32 + lane;

        // ---------- build A chunk 0 (bf16x2 math) ----------
        {
            const uint4* src = (const uint4*)hjrow;
            const uint4* hb  = (const uint4*)hibp;
            #pragma unroll
            for (int s = 0; s < 4; s++) {
                uint4 v = src[s];
                uint4 w = hb[s];
                uint4 o;
                o.x = hadd_relu2(v.x, w.x);
                o.y = hadd_relu2(v.y, w.y);
                o.z = hadd_relu2(v.z, w.z);
                o.w = hadd_relu2(v.w, w.w);
                *(uint4*)(abase_th + s * 16) = o;
            }
        }
        __syncthreads();

        for (int kc = 0; kc < 12; kc++) {
            const int cur = kc & 1;

            uint32_t bfr[4][4][2];
            #pragma unroll
            for (int nt = 0; nt < 4; nt++)
                #pragma unroll
                for (int ks = 0; ks < 4; ks++) {
                    uint2 v = bb[((long)nt * 48 + kc * 4 + ks) * 32];
                    bfr[nt][ks][0] = v.x;
                    bfr[nt][ks][1] = v.y;
                }

            if (kc < 11) {
                const int k0 = (kc + 1) * 64;
                const uint4* src = (const uint4*)(hjrow + k0);
                const uint4* hb  = (const uint4*)(hibp + k0);
                char* ab = abase_th + (cur ^ 1) * ABUF;
                #pragma unroll
                for (int s = 0; s < 4; s++) {
                    uint4 v = src[s];
                    uint4 w = hb[s];
                    uint4 o;
                    o.x = hadd_relu2(v.x, w.x);
                    o.y = hadd_relu2(v.y, w.y);
                    o.z = hadd_relu2(v.z, w.z);
                    o.w = hadd_relu2(v.w, w.w);
                    *(uint4*)(ab + s * 16) = o;
                }
            }

            const uint32_t abase = sbase + SM_A + cur * ABUF;
            #pragma unroll
            for (int ks = 0; ks < 4; ks++) {
                uint32_t afr[4][4];
                #pragma unroll
                for (int mt = 0; mt < 4; mt++) {
                    uint32_t addr = abase +
                        (warpM * 64 + mt * 16 + (lane & 15)) * APITCH +
                        (ks * 16 + (lane >> 4) * 8) * 2;
                    ldsm_x4(afr[mt][0], afr[mt][1], afr[mt][2], afr[mt][3], addr);
                }
                #pragma unroll
                for (int mt = 0; mt < 4; mt++)
                    #pragma unroll
                    for (int nt = 0; nt < 4; nt++)
                        mma_bf16(c[mt][nt], afr[mt], bfr[nt][ks]);
            }
            __syncthreads();
        }

        const int qr = lane >> 2;
        const int qc = lane & 3;
        #pragma unroll
        for (int mt = 0; mt < 4; mt++) {
            float p0 = 0.f, p1 = 0.f;
            #pragma unroll
            for (int nt = 0; nt < 4; nt++) {
                int n0 = nc * 128 + warpN * 32 + nt * 8 + qc * 2;
                float bw0 = b2s[n0], bw1 = b2s[n0 + 1];
                float ww0 = w3s[n0], ww1 = w3s[n0 + 1];
                p0 += fmaxf(c[mt][nt][0] + bw0, 0.f) * ww0
                    + fmaxf(c[mt][nt][1] + bw1, 0.f) * ww1;
                p1 += fmaxf(c[mt][nt][2] + bw0, 0.f) * ww0
                    + fmaxf(c[mt][nt][3] + bw1, 0.f) * ww1;
            }
            p0 += __shfl_xor_sync(0xffffffffu, p0, 1);
            p0 += __shfl_xor_sync(0xffffffffu, p0, 2);
            p1 += __shfl_xor_sync(0xffffffffu, p1, 1);
            p1 += __shfl_xor_sync(0xffffffffu, p1, 2);
            if (qc == 0) {
                atomicAdd(&scal[warpM * 64 + mt * 16 + qr], p0);
                atomicAdd(&scal[warpM * 64 + mt * 16 + qr + 8], p1);
            }
        }
        __syncthreads();
    }

    if (tid < 128) {
        float x  = scal[tid] + b3p[0];
        float ew = 1.f / (1.f + expf(-x));
        scal[tid] = adj[(long)bi * 128 + tid] * ew + (tid == i ? 1.f : 0.f);
    }
    __syncthreads();
    if (tid < 32) {
        float m = fmaxf(fmaxf(scal[tid], scal[tid + 32]),
                        fmaxf(scal[tid + 64], scal[tid + 96]));
        for (int sh = 16; sh; sh >>= 1) m = fmaxf(m, __shfl_xor_sync(0xffffffffu, m, sh));
        if (tid == 0) red[0] = m;
    }
    __syncthreads();
    if (tid < 128) scal[tid] = expf(scal[tid] - red[0]);
    __syncthreads();
    if (tid < 32) {
        float s = scal[tid] + scal[tid + 32] + scal[tid + 64] + scal[tid + 96];
        for (int sh = 16; sh; sh >>= 1) s += __shfl_xor_sync(0xffffffffu, s, sh);
        if (tid == 0) red[1] = s;
    }
    __syncthreads();
    if (tid < 128) {
        float p = scal[tid] / red[1];
        a_out[(long)bi * 128 + tid] = p + (tid == i ? 1.f : 0.f);
        scal[tid] = p;
    }
    __syncthreads();
    if (tid < 32) {
        float s = scal[tid] + scal[tid + 32] + scal[tid + 64] + scal[tid + 96];
        for (int sh = 16; sh; sh >>= 1) s += __shfl_xor_sync(0xffffffffu, s, sh);
        if (tid == 0) denom_out[bi] = 1.f + s;
    }
}

// ---------------- fused bias + denom + relu + LayerNorm ----------------------
__global__ __launch_bounds__(256)
void ln_kernel(const float* __restrict__ y, const float* __restrict__ gb,
               const float* __restrict__ lng, const float* __restrict__ lnb,
               const float* __restrict__ denom, float* __restrict__ outp)
{
    const int row = blockIdx.x;
    const int tid = threadIdx.x;
    const float inv = 1.f / denom[row];
    const float* yr = y + (long)row * DDIM;

    float v[3];
    float s = 0.f, sq = 0.f;
    #pragma unroll
    for (int p = 0; p < 3; p++) {
        int n = tid + p * 256;
        float x = fmaxf((yr[n] + 2.f * gb[n]) * inv, 0.f);
        v[p] = x; s += x; sq += x * x;
    }
    __shared__ float rs[8], rq[8], mm[2];
    for (int sh = 16; sh; sh >>= 1) {
        s  += __shfl_xor_sync(0xffffffffu, s,  sh);
        sq += __shfl_xor_sync(0xffffffffu, sq, sh);
    }
    if ((tid & 31) == 0) { rs[tid >> 5] = s; rq[tid >> 5] = sq; }
    __syncthreads();
    if (tid == 0) {
        float S = 0.f, Q = 0.f;
        #pragma unroll
        for (int q = 0; q < 8; q++) { S += rs[q]; Q += rq[q]; }
        float mean = S / (float)DDIM;
        float var  = Q / (float)DDIM - mean * mean;
        mm[0] = mean;
        mm[1] = rsqrtf(var + 1e-5f);
    }
    __syncthreads();
    const float mean = mm[0], rstd = mm[1];
    float* orow = outp + (long)row * DDIM;
    #pragma unroll
    for (int p = 0; p < 3; p++) {
        int n = tid + p * 256;
        orow[n] = (v[p] - mean) * rstd * lng[n] + lnb[n];
    }
}

// ---------------- zero mask tail ---------------------------------------------
__global__ void zero_tail_kernel(float* __restrict__ dst, int start, int total)
{
    int idx = start + blockIdx.x * 256 + threadIdx.x;
    if (idx < total) dst[idx] = 0.f;
}

// ---------------- launch ------------------------------------------------------
extern "C" void kernel_launch(void* const* d_in, const int* in_sizes, int n_in,
                              void* d_out, int out_size)
{
    const float* adj    = (const float*)d_in[0];
    const float* inputs = (const float*)d_in[1];
    const float* w1     = (const float*)d_in[2];
    const float* b1     = (const float*)d_in[3];
    const float* w2     = (const float*)d_in[4];
    const float* b2     = (const float*)d_in[5];
    const float* w3     = (const float*)d_in[6];
    const float* b3     = (const float*)d_in[7];
    const float* gw     = (const float*)d_in[8];
    const float* gb     = (const float*)d_in[9];
    const float* lng    = (const float*)d_in[10];
    const float* lnb    = (const float*)d_in[11];

    float *hi, *a, *denom, *y, *buf;
    __nv_bfloat16 *hj2, *tH, *tL;
    uint2 *bfrag, *gwfH, *gwfL;
    cudaGetSymbolAddress((void**)&hi,    g_hi);
    cudaGetSymbolAddress((void**)&a,     g_a);
    cudaGetSymbolAddress((void**)&denom, g_denom);
    cudaGetSymbolAddress((void**)&y,     g_y);
    cudaGetSymbolAddress((void**)&buf,   g_buf);
    cudaGetSymbolAddress((void**)&hj2,   g_hj2);
    cudaGetSymbolAddress((void**)&tH,    g_tH);
    cudaGetSymbolAddress((void**)&tL,    g_tL);
    cudaGetSymbolAddress((void**)&bfrag, g_bfrag);
    cudaGetSymbolAddress((void**)&gwfH,  g_gwfH);
    cudaGetSymbolAddress((void**)&gwfL,  g_gwfL);

    dim3 blk(256);

    // coalesced fragment prep: w2 (bf16) and gw (split-bf16)
    prep_frag<false><<<dim3(6, 48, 1), blk>>>(w2, 384, 0L, 0, bfrag, nullptr);
    prep_frag<true><<<dim3(12, 48, 3), blk>>>(gw, DDIM, (long)DDIM * DDIM, 96,
                                              gwfH, gwfL);

    // hi = X @ w1[:768] (fp32 out); hj = X @ w1[768:] (bf16 out, direct)
    gemm_tf32<128, false, 0><<<dim3(12, 8, 1), blk>>>(
        inputs, w1, hi, nullptr, nullptr, nullptr,
        ROWS, DDIM, DDIM, 0L, 0L, 0L);
    gemm_tf32<128, false, 2><<<dim3(12, 8, 1), blk>>>(
        inputs, w1 + (long)DDIM * DDIM, nullptr, nullptr, hj2, nullptr,
        ROWS, DDIM, DDIM, 0L, 0L, 0L);

    // fused edge MLP (bf16 tensor cores) + softmax -> a (= softmax + I), denom
    edge_mma_kernel<<<1024, blk>>>(hi, hj2, adj, b1, bfrag, b2, w3, b3, a, denom);

    const float* cur = inputs;
    for (int li = 0; li < 3; li++) {
        // t = (a + I) @ cur  (3xTF32 exact; epilogue emits bf16 hi/lo); 192 CTAs
        gemm_tf32<64, true, 1><<<dim3(12, 2, NBATCH), blk>>>(
            a, cur, nullptr, nullptr, tH, tL,
            LSEQ, DDIM, LSEQ,
            (long)LSEQ * LSEQ, (long)LSEQ * DDIM, (long)LSEQ * DDIM);
        // y = t @ gw[li]  (split-bf16 exact); 192 CTAs
        gemm_tgw<<<dim3(12, 16), blk>>>(tH, tL, gwfH, gwfL, li, y);
        float* nxt = (li == 2) ? (float*)d_out
                               : buf + (long)(li & 1) * ROWS * DDIM;
        ln_kernel<<<1024, blk>>>(y, gb + li * DDIM, lng + li * DDIM, lnb + li * DDIM,
                                 denom, nxt);
        cur = nxt;
    }

    int tail = out_size - ROWS * DDIM;
    if (tail > 0)
        zero_tail_kernel<<<(tail + 255) / 256, blk>>>((float*)d_out, ROWS * DDIM, out_size);
}

// round 12
// speedup vs baseline: 1.0304x; 1.0304x over previous
#include <cuda_runtime.h>
#include <cuda_bf16.h>
#include <cstdint>

#define LSEQ 128
#define DDIM 768
#define NBATCH 8
#define ROWS (NBATCH * LSEQ)   // 1024

// ---------------- scratch (__device__ globals; no allocation) ----------------
__device__ float g_hi[ROWS * DDIM];      // hi (fp32)
__device__ float g_a[NBATCH * LSEQ * LSEQ];
__device__ float g_denom[ROWS];
__device__ float g_y[ROWS * DDIM];
__device__ float g_buf[2][ROWS * DDIM];
__device__ __align__(16) __nv_bfloat16 g_hj2[ROWS * DDIM];  // hj bf16 (direct from GEMM)
__device__ __align__(16) __nv_bfloat16 g_tH[ROWS * DDIM];   // t split hi
__device__ __align__(16) __nv_bfloat16 g_tL[ROWS * DDIM];   // t split lo
// w2 fragments (m16n8k16 B order): [nn 0..47][kk 0..47][lane]
__device__ __align__(16) uint2 g_bfrag[48 * 48 * 32];
// gw split-bf16 fragments: [li*96 + nn][kk 0..47][lane]
__device__ __align__(16) uint2 g_gwfH[3 * 96 * 48 * 32];
__device__ __align__(16) uint2 g_gwfL[3 * 96 * 48 * 32];

// ============================================================================
// PTX helpers (baseline features only)
// ============================================================================
__device__ __forceinline__ uint32_t smem_to_u32(const void* p) {
    uint32_t a;
    asm("{ .reg .u64 t; cvta.to.shared.u64 t, %1; cvt.u32.u64 %0, t; }" : "=r"(a) : "l"(p));
    return a;
}
#define CP_ASYNC16(dst, src) \
    asm volatile("cp.async.cg.shared.global [%0], [%1], 16;" :: "r"(dst), "l"(src))
#define CP_COMMIT() asm volatile("cp.async.commit_group;" ::: "memory")
#define CP_WAIT0()  asm volatile("cp.async.wait_group 0;" ::: "memory")

__device__ __forceinline__ void ldsm_x4(uint32_t& r0, uint32_t& r1, uint32_t& r2,
                                        uint32_t& r3, uint32_t addr) {
    asm volatile("ldmatrix.sync.aligned.m8n8.x4.shared.b16 {%0,%1,%2,%3}, [%4];"
                 : "=r"(r0), "=r"(r1), "=r"(r2), "=r"(r3) : "r"(addr));
}
__device__ __forceinline__ void mma_bf16(float* c, const uint32_t* a, const uint32_t* b) {
    asm volatile("mma.sync.aligned.m16n8k16.row.col.f32.bf16.bf16.f32 "
                 "{%0,%1,%2,%3}, {%4,%5,%6,%7}, {%8,%9}, {%0,%1,%2,%3};"
                 : "+f"(c[0]), "+f"(c[1]), "+f"(c[2]), "+f"(c[3])
                 : "r"(a[0]), "r"(a[1]), "r"(a[2]), "r"(a[3]), "r"(b[0]), "r"(b[1]));
}
__device__ __forceinline__ void mma_tf32(float* c, const uint32_t* a, const uint32_t* b) {
    asm volatile("mma.sync.aligned.m16n8k8.row.col.f32.tf32.tf32.f32 "
                 "{%0,%1,%2,%3}, {%4,%5,%6,%7}, {%8,%9}, {%0,%1,%2,%3};"
                 : "+f"(c[0]), "+f"(c[1]), "+f"(c[2]), "+f"(c[3])
                 : "r"(a[0]), "r"(a[1]), "r"(a[2]), "r"(a[3]), "r"(b[0]), "r"(b[1]));
}
__device__ __forceinline__ uint32_t f2tf32(float x) {
    uint32_t r;
    asm("cvt.rna.tf32.f32 %0, %1;" : "=r"(r) : "f"(x));
    return r;
}
__device__ __forceinline__ void f2tf32x2(float x, uint32_t& hi, uint32_t& lo) {
    hi = f2tf32(x);
    lo = f2tf32(x - __uint_as_float(hi));
}
__device__ __forceinline__ uint32_t pack_bf16x2(float a, float b) {
    __nv_bfloat162 r = __floats2bfloat162_rn(a, b);
    return *(uint32_t*)&r;
}

// ============================================================================
// tf32 tensor GEMM: row-major. BM x 64 x BK=16 tiles.
// BM=128: 8 warps 4Mx2N. BM=64: 8 warps 2Mx4N.
// EXACT: 3xTF32.
// OMODE: 0 = fp32 C (+Cadd) | 1 = bf16 hi/lo split | 3 = dual: z=0 fp32 C,
//        z=1 bf16 outH (hi/hj fused launch; sC must be 0 so coff==0).
// ============================================================================
#define TAP 20
#define TBP 72

template <int BM, bool EXACT, int OMODE>
__global__ __launch_bounds__(256)
void gemm_tf32(const float* __restrict__ A, const float* __restrict__ B,
               float* __restrict__ C, const float* __restrict__ Cadd,
               __nv_bfloat16* __restrict__ outH, __nv_bfloat16* __restrict__ outL,
               int M, int N, int K, long sA, long sB, long sC)
{
    constexpr int WN = (BM == 128) ? 2 : 4;
    constexpr int NT = (BM == 128) ? 4 : 2;

    const int bz = blockIdx.z;
    A += (long)bz * sA;
    B += (long)bz * sB;
    const long coff = (long)bz * sC;

    const int bm = blockIdx.y * BM;
    const int bn = blockIdx.x * 64;

    __shared__ float As[2][BM][TAP];
    __shared__ float Bs[2][16][TBP];

    const int tid  = threadIdx.x;
    const int lane = tid & 31;
    const int wid  = tid >> 5;
    const int warpM = wid / WN;
    const int warpN = wid % WN;
    const int gr = lane >> 2;
    const int gc = lane & 3;

    const uint32_t sbase = smem_to_u32(&As[0][0][0]);
    const uint32_t bbase = smem_to_u32(&Bs[0][0][0]);

    const int arow = (BM == 128) ? (tid >> 1) : (tid >> 2);
    const int akq  = (BM == 128) ? ((tid & 1) * 8) : ((tid & 3) * 4);
    const int bk   = tid >> 4;
    const int bn4  = (tid & 15) * 4;

    const int nK = K >> 4;

    {
        const float* as = A + (long)(bm + arow) * K + akq;
        uint32_t ad = sbase + (arow * TAP + akq) * 4;
        CP_ASYNC16(ad, as);
        if (BM == 128) CP_ASYNC16(ad + 16, as + 4);
        const float* bs = B + (long)bk * N + bn + bn4;
        uint32_t bd = bbase + (bk * TBP + bn4) * 4;
        CP_ASYNC16(bd, bs);
        CP_COMMIT();
    }

    float c[2][NT][4];
    #pragma unroll
    for (int mt = 0; mt < 2; mt++)
        #pragma unroll
        for (int nt = 0; nt < NT; nt++)
            #pragma unroll
            for (int q = 0; q < 4; q++) c[mt][nt][q] = 0.f;

    for (int ki = 0; ki < nK; ki++) {
        CP_WAIT0();
        __syncthreads();
        const int cur = ki & 1;
        if (ki + 1 < nK) {
            const int nxt = cur ^ 1;
            const int kc = (ki + 1) * 16;
            const float* as = A + (long)(bm + arow) * K + kc + akq;
            uint32_t ad = sbase + (nxt * BM * TAP + arow * TAP + akq) * 4;
            CP_ASYNC16(ad, as);
            if (BM == 128) CP_ASYNC16(ad + 16, as + 4);
            const float* bs = B + (long)(kc + bk) * N + bn + bn4;
            uint32_t bd = bbase + (nxt * 16 * TBP + bk * TBP + bn4) * 4;
            CP_ASYNC16(bd, bs);
            CP_COMMIT();
        }

        #pragma unroll
        for (int k8 = 0; k8 < 16; k8 += 8) {
            uint32_t ah[2][4], al[2][4];
            #pragma unroll
            for (int mt = 0; mt < 2; mt++) {
                int r0 = warpM * 32 + mt * 16 + gr;
                float v0 = As[cur][r0    ][k8 + gc];
                float v1 = As[cur][r0 + 8][k8 + gc];
                float v2 = As[cur][r0    ][k8 + gc + 4];
                float v3 = As[cur][r0 + 8][k8 + gc + 4];
                if (EXACT) {
                    f2tf32x2(v0, ah[mt][0], al[mt][0]);
                    f2tf32x2(v1, ah[mt][1], al[mt][1]);
                    f2tf32x2(v2, ah[mt][2], al[mt][2]);
                    f2tf32x2(v3, ah[mt][3], al[mt][3]);
                } else {
                    ah[mt][0] = f2tf32(v0); ah[mt][1] = f2tf32(v1);
                    ah[mt][2] = f2tf32(v2); ah[mt][3] = f2tf32(v3);
                }
            }
            uint32_t bh[NT][2], bl[NT][2];
            #pragma unroll
            for (int nt = 0; nt < NT; nt++) {
                int n = warpN * (NT * 8) + nt * 8 + gr;
                float v0 = Bs[cur][k8 + gc    ][n];
                float v1 = Bs[cur][k8 + gc + 4][n];
                if (EXACT) {
                    f2tf32x2(v0, bh[nt][0], bl[nt][0]);
                    f2tf32x2(v1, bh[nt][1], bl[nt][1]);
                } else {
                    bh[nt][0] = f2tf32(v0); bh[nt][1] = f2tf32(v1);
                }
            }
            #pragma unroll
            for (int mt = 0; mt < 2; mt++)
                #pragma unroll
                for (int nt = 0; nt < NT; nt++) {
                    if (EXACT) {
                        mma_tf32(c[mt][nt], al[mt], bh[nt]);
                        mma_tf32(c[mt][nt], ah[mt], bl[nt]);
                    }
                    mma_tf32(c[mt][nt], ah[mt], bh[nt]);
                }
        }
    }

    #pragma unroll
    for (int mt = 0; mt < 2; mt++) {
        #pragma unroll
        for (int nt = 0; nt < NT; nt++) {
            int row0 = bm + warpM * 32 + mt * 16 + gr;
            int col  = bn + warpN * (NT * 8) + nt * 8 + gc * 2;
            long o0 = coff + (long)row0 * N + col;
            long o1 = coff + (long)(row0 + 8) * N + col;
            float2 v0 = make_float2(c[mt][nt][0], c[mt][nt][1]);
            float2 v1 = make_float2(c[mt][nt][2], c[mt][nt][3]);
            if (OMODE == 1) {
                float h0 = __bfloat162float(__float2bfloat16(v0.x));
                float h1 = __bfloat162float(__float2bfloat16(v0.y));
                float h2 = __bfloat162float(__float2bfloat16(v1.x));
                float h3 = __bfloat162float(__float2bfloat16(v1.y));
                ((uint32_t*)outH)[o0 >> 1] = pack_bf16x2(h0, h1);
                ((uint32_t*)outH)[o1 >> 1] = pack_bf16x2(h2, h3);
                ((uint32_t*)outL)[o0 >> 1] = pack_bf16x2(v0.x - h0, v0.y - h1);
                ((uint32_t*)outL)[o1 >> 1] = pack_bf16x2(v1.x - h2, v1.y - h3);
            } else if (OMODE == 3) {
                if (bz == 0) {
                    *(float2*)(C + o0) = v0;
                    *(float2*)(C + o1) = v1;
                } else {
                    ((uint32_t*)outH)[o0 >> 1] = pack_bf16x2(v0.x, v0.y);
                    ((uint32_t*)outH)[o1 >> 1] = pack_bf16x2(v1.x, v1.y);
                }
            } else {
                if (Cadd) {
                    float2 w0 = *(const float2*)(Cadd + o0);
                    float2 w1 = *(const float2*)(Cadd + o1);
                    v0.x += w0.x; v0.y += w0.y;
                    v1.x += w1.x; v1.y += w1.y;
                }
                *(float2*)(C + o0) = v0;
                *(float2*)(C + o1) = v1;
            }
        }
    }
}

// ============================================================================
// split-bf16 GEMM for y = t @ gw[li]. BM=64, BN=64, BK=32; 192 CTAs.
// ============================================================================
#define TGP 80
#define TGB 5120

__global__ __launch_bounds__(256, 4)
void gemm_tgw(const __nv_bfloat16* __restrict__ tH, const __nv_bfloat16* __restrict__ tL,
              const uint2* __restrict__ gwfH, const uint2* __restrict__ gwfL,
              int li, float* __restrict__ y)
{
    __shared__ __align__(16) char smem[2 * 2 * TGB];
    const uint32_t sbase = smem_to_u32(smem);
    const int tid  = threadIdx.x;
    const int lane = tid & 31;
    const int wid  = tid >> 5;
    const int warpM = wid >> 2;
    const int warpN = wid & 3;
    const int bm = blockIdx.y * 64;
    const int bn = blockIdx.x * 64;

    const int srow = tid >> 2;
    const int spart = tid & 3;

    {
        uint32_t d = sbase + srow * TGP + spart * 16;
        CP_ASYNC16(d, tH + (long)(bm + srow) * DDIM + spart * 8);
        CP_ASYNC16(d + TGB, tL + (long)(bm + srow) * DDIM + spart * 8);
        CP_COMMIT();
    }

    float c[2][2][4];
    #pragma unroll
    for (int mt = 0; mt < 2; mt++)
        #pragma unroll
        for (int nt = 0; nt < 2; nt++)
            #pragma unroll
            for (int q = 0; q < 4; q++) c[mt][nt][q] = 0.f;

    const long nnb = (long)li * 96 + blockIdx.x * 8 + warpN * 2;

    for (int kc = 0; kc < 24; kc++) {
        CP_WAIT0();
        __syncthreads();
        const int cur = kc & 1;
        if (kc < 23) {
            const int k0 = (kc + 1) * 32;
            uint32_t d = sbase + (cur ^ 1) * 2 * TGB + srow * TGP + spart * 16;
            CP_ASYNC16(d, tH + (long)(bm + srow) * DDIM + k0 + spart * 8);
            CP_ASYNC16(d + TGB, tL + (long)(bm + srow) * DDIM + k0 + spart * 8);
            CP_COMMIT();
        }

        #pragma unroll
        for (int ks = 0; ks < 2; ks++) {
            const int kkg = kc * 2 + ks;
            uint32_t bh[2][2], bl[2][2];
            #pragma unroll
            for (int nt = 0; nt < 2; nt++) {
                uint2 v = gwfH[((nnb + nt) * 48 + kkg) * 32 + lane];
                bh[nt][0] = v.x; bh[nt][1] = v.y;
                v = gwfL[((nnb + nt) * 48 + kkg) * 32 + lane];
                bl[nt][0] = v.x; bl[nt][1] = v.y;
            }
            #pragma unroll
            for (int mt = 0; mt < 2; mt++) {
                uint32_t addr = sbase + cur * 2 * TGB +
                    (warpM * 32 + mt * 16 + (lane & 15)) * TGP +
                    (lane >> 4) * 16 + ks * 32;
                uint32_t ahf[4], alf[4];
                ldsm_x4(ahf[0], ahf[1], ahf[2], ahf[3], addr);
                ldsm_x4(alf[0], alf[1], alf[2], alf[3], addr + TGB);
                #pragma unroll
                for (int nt = 0; nt < 2; nt++) {
                    mma_bf16(c[mt][nt], ahf, bh[nt]);
                    mma_bf16(c[mt][nt], alf, bh[nt]);
                    mma_bf16(c[mt][nt], ahf, bl[nt]);
                }
            }
        }
    }

    const int gr = lane >> 2;
    const int gc = lane & 3;
    #pragma unroll
    for (int mt = 0; mt < 2; mt++)
        #pragma unroll
        for (int nt = 0; nt < 2; nt++) {
            int row0 = bm + warpM * 32 + mt * 16 + gr;
            int col  = bn + warpN * 16 + nt * 8 + gc * 2;
            *(float2*)(y + (long)row0 * DDIM + col) =
                make_float2(c[mt][nt][0], c[mt][nt][1]);
            *(float2*)(y + (long)(row0 + 8) * DDIM + col) =
                make_float2(c[mt][nt][2], c[mt][nt][3]);
        }
}

// ============================================================================
// Coalesced fragment prep (smem-staged transpose).
// ============================================================================
template <bool SPLIT>
__global__ void prep_frag(const float* __restrict__ src, int srcN, long srcStride,
                          int nnPerZ, uint2* __restrict__ dstH, uint2* __restrict__ dstL)
{
    __shared__ float tile[16][68];
    const int tid = threadIdx.x;
    const float* S = src + (long)blockIdx.z * srcStride;

    {
        int row = tid >> 4;
        int col4 = (tid & 15) * 4;
        float4 v = *(const float4*)(S + (long)(blockIdx.y * 16 + row) * srcN
                                    + blockIdx.x * 64 + col4);
        tile[row][col4 + 0] = v.x;
        tile[row][col4 + 1] = v.y;
        tile[row][col4 + 2] = v.z;
        tile[row][col4 + 3] = v.w;
    }
    __syncthreads();

    const int nn_local = tid >> 5;
    const int lane = tid & 31;
    const int n_l = nn_local * 8 + (lane >> 2);
    const int r0 = 2 * (lane & 3);
    float g0 = tile[r0][n_l],     g1 = tile[r0 + 1][n_l];
    float g2 = tile[r0 + 8][n_l], g3 = tile[r0 + 9][n_l];

    long nnG = (long)blockIdx.z * nnPerZ + blockIdx.x * 8 + nn_local;
    long idx = (nnG * 48 + blockIdx.y) * 32 + lane;

    if (SPLIT) {
        float h0 = __bfloat162float(__float2bfloat16(g0));
        float h1 = __bfloat162float(__float2bfloat16(g1));
        float h2 = __bfloat162float(__float2bfloat16(g2));
        float h3 = __bfloat162float(__float2bfloat16(g3));
        uint2 H, L;
        H.x = pack_bf16x2(h0, h1);           H.y = pack_bf16x2(h2, h3);
        L.x = pack_bf16x2(g0 - h0, g1 - h1); L.y = pack_bf16x2(g2 - h2, g3 - h3);
        dstH[idx] = H;
        dstL[idx] = L;
    } else {
        uint2 H;
        H.x = pack_bf16x2(g0, g1);
        H.y = pack_bf16x2(g2, g3);
        dstH[idx] = H;
    }
}

// ============================================================================
// Fused edge-MLP via mma.sync bf16 (R10 proven version). One CTA/(b,i).
// fp32 hib A-build; B frags from global; double-buffered A; 2 CTAs/SM.
// ============================================================================
#define APITCH 144
#define ABUF   18432
#define SM_A     0
#define SM_HIB   36864
#define SM_B2    39936
#define SM_W3    41472
#define SM_SCAL  43008
#define SM_RED   43520
#define SM_TOTAL 43584

__global__ __launch_bounds__(256, 2)
void edge_mma_kernel(const float* __restrict__ hi, const __nv_bfloat16* __restrict__ hj2,
                     const float* __restrict__ adj, const float* __restrict__ b1,
                     const uint2* __restrict__ bfrag, const float* __restrict__ b2,
                     const float* __restrict__ w3, const float* __restrict__ b3p,
                     float* __restrict__ a_out, float* __restrict__ denom_out)
{
    __shared__ __align__(16) char smem[SM_TOTAL];
    const uint32_t sbase = smem_to_u32(smem);
    const int tid  = threadIdx.x;
    const int lane = tid & 31;
    const int wid  = tid >> 5;
    const int warpM = wid >> 2;
    const int warpN = wid & 3;
    const int bi = blockIdx.x;
    const int b  = bi >> 7;
    const int i  = bi & 127;

    float* hib  = (float*)(smem + SM_HIB);
    float* b2s  = (float*)(smem + SM_B2);
    float* w3s  = (float*)(smem + SM_W3);
    float* scal = (float*)(smem + SM_SCAL);
    float* red  = (float*)(smem + SM_RED);

    for (int k = tid; k < DDIM; k += 256) hib[k] = hi[(long)bi * DDIM + k] + b1[k];
    for (int k = tid; k < 384; k += 256) { b2s[k] = b2[k]; w3s[k] = w3[k]; }
    if (tid < 128) scal[tid] = 0.f;
    __syncthreads();

    const int aj = tid >> 1;
    const int ahh = tid & 1;
    const __nv_bfloat16* hjrow = hj2 + ((long)b * LSEQ + aj) * DDIM + ahh * 32;
    char* abase_th = smem + SM_A + aj * APITCH + ahh * 64;

    for (int nc = 0; nc < 3; nc++) {
        float c[4][4][4];
        #pragma unroll
        for (int mt = 0; mt < 4; mt++)
            #pragma unroll
            for (int nt = 0; nt < 4; nt++)
                #pragma unroll
                for (int q = 0; q < 4; q++) c[mt][nt][q] = 0.f;

        const uint2* bb = bfrag + ((long)(nc * 16 + warpN * 4) * 48) * 32 + lane;

        {
            const uint4* src = (const uint4*)hjrow;
            const float* hb  = hib + ahh * 32;
            #pragma unroll
            for (int s = 0; s < 4; s++) {
                uint4 v = src[s];
                __nv_bfloat162* p = (__nv_bfloat162*)&v;
                uint4 o;
                uint32_t* po = (uint32_t*)&o;
                #pragma unroll
                for (int h = 0; h < 4; h++) {
                    float2 f = __bfloat1622float2(p[h]);
                    po[h] = pack_bf16x2(fmaxf(f.x + hb[s * 8 + h * 2], 0.f),
                                        fmaxf(f.y + hb[s * 8 + h * 2 + 1], 0.f));
                }
                *(uint4*)(abase_th + s * 16) = o;
            }
        }
        __syncthreads();

        for (int kc = 0; kc < 12; kc++) {
            const int cur = kc & 1;

            uint32_t bfr[4][4][2];
            #pragma unroll
            for (int nt = 0; nt < 4; nt++)
                #pragma unroll
                for (int ks = 0; ks < 4; ks++) {
                    uint2 v = bb[((long)nt * 48 + kc * 4 + ks) * 32];
                    bfr[nt][ks][0] = v.x;
                    bfr[nt][ks][1] = v.y;
                }

            if (kc < 11) {
                const int k0 = (kc + 1) * 64;
                const uint4* src = (const uint4*)(hjrow + k0);
                const float* hb  = hib + k0 + ahh * 32;
                char* ab = abase_th + (cur ^ 1) * ABUF;
                #pragma unroll
                for (int s = 0; s < 4; s++) {
                    uint4 v = src[s];
                    __nv_bfloat162* p = (__nv_bfloat162*)&v;
                    uint4 o;
                    uint32_t* po = (uint32_t*)&o;
                    #pragma unroll
                    for (int h = 0; h < 4; h++) {
                        float2 f = __bfloat1622float2(p[h]);
                        po[h] = pack_bf16x2(fmaxf(f.x + hb[s * 8 + h * 2], 0.f),
                                            fmaxf(f.y + hb[s * 8 + h * 2 + 1], 0.f));
                    }
                    *(uint4*)(ab + s * 16) = o;
                }
            }

            const uint32_t abase = sbase + SM_A + cur * ABUF;
            #pragma unroll
            for (int ks = 0; ks < 4; ks++) {
                uint32_t afr[4][4];
                #pragma unroll
                for (int mt = 0; mt < 4; mt++) {
                    uint32_t addr = abase +
                        (warpM * 64 + mt * 16 + (lane & 15)) * APITCH +
                        (ks * 16 + (lane >> 4) * 8) * 2;
                    ldsm_x4(afr[mt][0], afr[mt][1], afr[mt][2], afr[mt][3], addr);
                }
                #pragma unroll
                for (int mt = 0; mt < 4; mt++)
                    #pragma unroll
                    for (int nt = 0; nt < 4; nt++)
                        mma_bf16(c[mt][nt], afr[mt], bfr[nt][ks]);
            }
            __syncthreads();
        }

        const int qr = lane >> 2;
        const int qc = lane & 3;
        #pragma unroll
        for (int mt = 0; mt < 4; mt++) {
            float p0 = 0.f, p1 = 0.f;
            #pragma unroll
            for (int nt = 0; nt < 4; nt++) {
                int n0 = nc * 128 + warpN * 32 + nt * 8 + qc * 2;
                float bw0 = b2s[n0], bw1 = b2s[n0 + 1];
                float ww0 = w3s[n0], ww1 = w3s[n0 + 1];
                p0 += fmaxf(c[mt][nt][0] + bw0, 0.f) * ww0
                    + fmaxf(c[mt][nt][1] + bw1, 0.f) * ww1;
                p1 += fmaxf(c[mt][nt][2] + bw0, 0.f) * ww0
                    + fmaxf(c[mt][nt][3] + bw1, 0.f) * ww1;
            }
            p0 += __shfl_xor_sync(0xffffffffu, p0, 1);
            p0 += __shfl_xor_sync(0xffffffffu, p0, 2);
            p1 += __shfl_xor_sync(0xffffffffu, p1, 1);
            p1 += __shfl_xor_sync(0xffffffffu, p1, 2);
            if (qc == 0) {
                atomicAdd(&scal[warpM * 64 + mt * 16 + qr], p0);
                atomicAdd(&scal[warpM * 64 + mt * 16 + qr + 8], p1);
            }
        }
        __syncthreads();
    }

    if (tid < 128) {
        float x  = scal[tid] + b3p[0];
        float ew = 1.f / (1.f + expf(-x));
        scal[tid] = adj[(long)bi * 128 + tid] * ew + (tid == i ? 1.f : 0.f);
    }
    __syncthreads();
    if (tid < 32) {
        float m = fmaxf(fmaxf(scal[tid], scal[tid + 32]),
                        fmaxf(scal[tid + 64], scal[tid + 96]));
        for (int sh = 16; sh; sh >>= 1) m = fmaxf(m, __shfl_xor_sync(0xffffffffu, m, sh));
        if (tid == 0) red[0] = m;
    }
    __syncthreads();
    if (tid < 128) scal[tid] = expf(scal[tid] - red[0]);
    __syncthreads();
    if (tid < 32) {
        float s = scal[tid] + scal[tid + 32] + scal[tid + 64] + scal[tid + 96];
        for (int sh = 16; sh; sh >>= 1) s += __shfl_xor_sync(0xffffffffu, s, sh);
        if (tid == 0) red[1] = s;
    }
    __syncthreads();
    if (tid < 128) {
        float p = scal[tid] / red[1];
        a_out[(long)bi * 128 + tid] = p + (tid == i ? 1.f : 0.f);
        scal[tid] = p;
    }
    __syncthreads();
    if (tid < 32) {
        float s = scal[tid] + scal[tid + 32] + scal[tid + 64] + scal[tid + 96];
        for (int sh = 16; sh; sh >>= 1) s += __shfl_xor_sync(0xffffffffu, s, sh);
        if (tid == 0) denom_out[bi] = 1.f + s;
    }
}

// ---------------- fused bias + denom + relu + LayerNorm ----------------------
__global__ __launch_bounds__(256)
void ln_kernel(const float* __restrict__ y, const float* __restrict__ gb,
               const float* __restrict__ lng, const float* __restrict__ lnb,
               const float* __restrict__ denom, float* __restrict__ outp)
{
    const int row = blockIdx.x;
    const int tid = threadIdx.x;
    const float inv = 1.f / denom[row];
    const float* yr = y + (long)row * DDIM;

    float v[3];
    float s = 0.f, sq = 0.f;
    #pragma unroll
    for (int p = 0; p < 3; p++) {
        int n = tid + p * 256;
        float x = fmaxf((yr[n] + 2.f * gb[n]) * inv, 0.f);
        v[p] = x; s += x; sq += x * x;
    }
    __shared__ float rs[8], rq[8], mm[2];
    for (int sh = 16; sh; sh >>= 1) {
        s  += __shfl_xor_sync(0xffffffffu, s,  sh);
        sq += __shfl_xor_sync(0xffffffffu, sq, sh);
    }
    if ((tid & 31) == 0) { rs[tid >> 5] = s; rq[tid >> 5] = sq; }
    __syncthreads();
    if (tid == 0) {
        float S = 0.f, Q = 0.f;
        #pragma unroll
        for (int q = 0; q < 8; q++) { S += rs[q]; Q += rq[q]; }
        float mean = S / (float)DDIM;
        float var  = Q / (float)DDIM - mean * mean;
        mm[0] = mean;
        mm[1] = rsqrtf(var + 1e-5f);
    }
    __syncthreads();
    const float mean = mm[0], rstd = mm[1];
    float* orow = outp + (long)row * DDIM;
    #pragma unroll
    for (int p = 0; p < 3; p++) {
        int n = tid + p * 256;
        orow[n] = (v[p] - mean) * rstd * lng[n] + lnb[n];
    }
}

// ---------------- zero mask tail ---------------------------------------------
__global__ void zero_tail_kernel(float* __restrict__ dst, int start, int total)
{
    int idx = start + blockIdx.x * 256 + threadIdx.x;
    if (idx < total) dst[idx] = 0.f;
}

// ---------------- launch ------------------------------------------------------
extern "C" void kernel_launch(void* const* d_in, const int* in_sizes, int n_in,
                              void* d_out, int out_size)
{
    const float* adj    = (const float*)d_in[0];
    const float* inputs = (const float*)d_in[1];
    const float* w1     = (const float*)d_in[2];
    const float* b1     = (const float*)d_in[3];
    const float* w2     = (const float*)d_in[4];
    const float* b2     = (const float*)d_in[5];
    const float* w3     = (const float*)d_in[6];
    const float* b3     = (const float*)d_in[7];
    const float* gw     = (const float*)d_in[8];
    const float* gb     = (const float*)d_in[9];
    const float* lng    = (const float*)d_in[10];
    const float* lnb    = (const float*)d_in[11];

    float *hi, *a, *denom, *y, *buf;
    __nv_bfloat16 *hj2, *tH, *tL;
    uint2 *bfrag, *gwfH, *gwfL;
    cudaGetSymbolAddress((void**)&hi,    g_hi);
    cudaGetSymbolAddress((void**)&a,     g_a);
    cudaGetSymbolAddress((void**)&denom, g_denom);
    cudaGetSymbolAddress((void**)&y,     g_y);
    cudaGetSymbolAddress((void**)&buf,   g_buf);
    cudaGetSymbolAddress((void**)&hj2,   g_hj2);
    cudaGetSymbolAddress((void**)&tH,    g_tH);
    cudaGetSymbolAddress((void**)&tL,    g_tL);
    cudaGetSymbolAddress((void**)&bfrag, g_bfrag);
    cudaGetSymbolAddress((void**)&gwfH,  g_gwfH);
    cudaGetSymbolAddress((void**)&gwfL,  g_gwfL);

    dim3 blk(256);

    // coalesced fragment prep: w2 (bf16) and gw (split-bf16)
    prep_frag<false><<<dim3(6, 48, 1), blk>>>(w2, 384, 0L, 0, bfrag, nullptr);
    prep_frag<true><<<dim3(12, 48, 3), blk>>>(gw, DDIM, (long)DDIM * DDIM, 96,
                                              gwfH, gwfL);

    // hi = X @ w1[:768] (fp32), hj = X @ w1[768:] (bf16, direct) — ONE 192-CTA launch
    gemm_tf32<128, false, 3><<<dim3(12, 8, 2), blk>>>(
        inputs, w1, hi, nullptr, hj2, nullptr,
        ROWS, DDIM, DDIM, 0L, (long)DDIM * DDIM, 0L);

    // fused edge MLP (bf16 tensor cores) + softmax -> a (= softmax + I), denom
    edge_mma_kernel<<<1024, blk>>>(hi, hj2, adj, b1, bfrag, b2, w3, b3, a, denom);

    const float* cur = inputs;
    for (int li = 0; li < 3; li++) {
        // t = (a + I) @ cur  (3xTF32 exact; epilogue emits bf16 hi/lo); 192 CTAs
        gemm_tf32<64, true, 1><<<dim3(12, 2, NBATCH), blk>>>(
            a, cur, nullptr, nullptr, tH, tL,
            LSEQ, DDIM, LSEQ,
            (long)LSEQ * LSEQ, (long)LSEQ * DDIM, (long)LSEQ * DDIM);
        // y = t @ gw[li]  (split-bf16 exact); 192 CTAs
        gemm_tgw<<<dim3(12, 16), blk>>>(tH, tL, gwfH, gwfL, li, y);
        float* nxt = (li == 2) ? (float*)d_out
                               : buf + (long)(li & 1) * ROWS * DDIM;
        ln_kernel<<<1024, blk>>>(y, gb + li * DDIM, lng + li * DDIM, lnb + li * DDIM,
                                 denom, nxt);
        cur = nxt;
    }

    int tail = out_size - ROWS * DDIM;
    if (tail > 0)
        zero_tail_kernel<<<(tail + 255) / 256, blk>>>((float*)d_out, ROWS * DDIM, out_size);
}

// round 14
// speedup vs baseline: 1.5570x; 1.5110x over previous
#include <cuda_runtime.h>
#include <cuda_bf16.h>
#include <cstdint>

#define LSEQ 128
#define DDIM 768
#define NBATCH 8
#define ROWS (NBATCH * LSEQ)   // 1024

// ---------------- scratch (__device__ globals; no allocation) ----------------
__device__ float g_hi[ROWS * DDIM];      // hi (fp32)
__device__ float g_a[NBATCH * LSEQ * LSEQ];
__device__ float g_denom[ROWS];
__device__ float g_y[ROWS * DDIM];
__device__ float g_buf[2][ROWS * DDIM];
__device__ __align__(16) __nv_bfloat16 g_hj2[ROWS * DDIM];  // hj bf16 (direct from GEMM)
__device__ __align__(16) __nv_bfloat16 g_tH[ROWS * DDIM];   // t split hi
__device__ __align__(16) __nv_bfloat16 g_tL[ROWS * DDIM];   // t split lo
// w2 fragments (m16n8k16 B order): [nn 0..47][kk 0..47][lane]
__device__ __align__(16) uint2 g_bfrag[48 * 48 * 32];
// gw split-bf16 fragments: [li*96 + nn][kk 0..47][lane]
__device__ __align__(16) uint2 g_gwfH[3 * 96 * 48 * 32];
__device__ __align__(16) uint2 g_gwfL[3 * 96 * 48 * 32];

// ============================================================================
// PTX helpers (baseline features only)
// ============================================================================
__device__ __forceinline__ uint32_t smem_to_u32(const void* p) {
    uint32_t a;
    asm("{ .reg .u64 t; cvta.to.shared.u64 t, %1; cvt.u32.u64 %0, t; }" : "=r"(a) : "l"(p));
    return a;
}
#define CP_ASYNC16(dst, src) \
    asm volatile("cp.async.cg.shared.global [%0], [%1], 16;" :: "r"(dst), "l"(src))
#define CP_COMMIT() asm volatile("cp.async.commit_group;" ::: "memory")
#define CP_WAIT0()  asm volatile("cp.async.wait_group 0;" ::: "memory")

__device__ __forceinline__ void ldsm_x4(uint32_t& r0, uint32_t& r1, uint32_t& r2,
                                        uint32_t& r3, uint32_t addr) {
    asm volatile("ldmatrix.sync.aligned.m8n8.x4.shared.b16 {%0,%1,%2,%3}, [%4];"
                 : "=r"(r0), "=r"(r1), "=r"(r2), "=r"(r3) : "r"(addr));
}
__device__ __forceinline__ void mma_bf16(float* c, const uint32_t* a, const uint32_t* b) {
    asm volatile("mma.sync.aligned.m16n8k16.row.col.f32.bf16.bf16.f32 "
                 "{%0,%1,%2,%3}, {%4,%5,%6,%7}, {%8,%9}, {%0,%1,%2,%3};"
                 : "+f"(c[0]), "+f"(c[1]), "+f"(c[2]), "+f"(c[3])
                 : "r"(a[0]), "r"(a[1]), "r"(a[2]), "r"(a[3]), "r"(b[0]), "r"(b[1]));
}
__device__ __forceinline__ void mma_tf32(float* c, const uint32_t* a, const uint32_t* b) {
    asm volatile("mma.sync.aligned.m16n8k8.row.col.f32.tf32.tf32.f32 "
                 "{%0,%1,%2,%3}, {%4,%5,%6,%7}, {%8,%9}, {%0,%1,%2,%3};"
                 : "+f"(c[0]), "+f"(c[1]), "+f"(c[2]), "+f"(c[3])
                 : "r"(a[0]), "r"(a[1]), "r"(a[2]), "r"(a[3]), "r"(b[0]), "r"(b[1]));
}
__device__ __forceinline__ uint32_t f2tf32(float x) {
    uint32_t r;
    asm("cvt.rna.tf32.f32 %0, %1;" : "=r"(r) : "f"(x));
    return r;
}
__device__ __forceinline__ void f2tf32x2(float x, uint32_t& hi, uint32_t& lo) {
    hi = f2tf32(x);
    lo = f2tf32(x - __uint_as_float(hi));
}
__device__ __forceinline__ uint32_t pack_bf16x2(float a, float b) {
    __nv_bfloat162 r = __floats2bfloat162_rn(a, b);
    return *(uint32_t*)&r;
}

// ============================================================================
// tf32 tensor GEMM: row-major. BM x 64 x BK=16 tiles.
// BM=128: 8 warps 4Mx2N. BM=64: 8 warps 2Mx4N.
// EXACT: 3xTF32.
// OMODE: 0 = fp32 C (+Cadd) | 1 = bf16 hi/lo split | 3 = dual: z=0 fp32 C,
//        z=1 bf16 outH (hi/hj fused launch; sC must be 0 so coff==0).
// ============================================================================
#define TAP 20
#define TBP 72

template <int BM, bool EXACT, int OMODE>
__global__ __launch_bounds__(256)
void gemm_tf32(const float* __restrict__ A, const float* __restrict__ B,
               float* __restrict__ C, const float* __restrict__ Cadd,
               __nv_bfloat16* __restrict__ outH, __nv_bfloat16* __restrict__ outL,
               int M, int N, int K, long sA, long sB, long sC)
{
    constexpr int WN = (BM == 128) ? 2 : 4;
    constexpr int NT = (BM == 128) ? 4 : 2;

    const int bz = blockIdx.z;
    A += (long)bz * sA;
    B += (long)bz * sB;
    const long coff = (long)bz * sC;

    const int bm = blockIdx.y * BM;
    const int bn = blockIdx.x * 64;

    __shared__ float As[2][BM][TAP];
    __shared__ float Bs[2][16][TBP];

    const int tid  = threadIdx.x;
    const int lane = tid & 31;
    const int wid  = tid >> 5;
    const int warpM = wid / WN;
    const int warpN = wid % WN;
    const int gr = lane >> 2;
    const int gc = lane & 3;

    const uint32_t sbase = smem_to_u32(&As[0][0][0]);
    const uint32_t bbase = smem_to_u32(&Bs[0][0][0]);

    const int arow = (BM == 128) ? (tid >> 1) : (tid >> 2);
    const int akq  = (BM == 128) ? ((tid & 1) * 8) : ((tid & 3) * 4);
    const int bk   = tid >> 4;
    const int bn4  = (tid & 15) * 4;

    const int nK = K >> 4;

    {
        const float* as = A + (long)(bm + arow) * K + akq;
        uint32_t ad = sbase + (arow * TAP + akq) * 4;
        CP_ASYNC16(ad, as);
        if (BM == 128) CP_ASYNC16(ad + 16, as + 4);
        const float* bs = B + (long)bk * N + bn + bn4;
        uint32_t bd = bbase + (bk * TBP + bn4) * 4;
        CP_ASYNC16(bd, bs);
        CP_COMMIT();
    }

    float c[2][NT][4];
    #pragma unroll
    for (int mt = 0; mt < 2; mt++)
        #pragma unroll
        for (int nt = 0; nt < NT; nt++)
            #pragma unroll
            for (int q = 0; q < 4; q++) c[mt][nt][q] = 0.f;

    for (int ki = 0; ki < nK; ki++) {
        CP_WAIT0();
        __syncthreads();
        const int cur = ki & 1;
        if (ki + 1 < nK) {
            const int nxt = cur ^ 1;
            const int kc = (ki + 1) * 16;
            const float* as = A + (long)(bm + arow) * K + kc + akq;
            uint32_t ad = sbase + (nxt * BM * TAP + arow * TAP + akq) * 4;
            CP_ASYNC16(ad, as);
            if (BM == 128) CP_ASYNC16(ad + 16, as + 4);
            const float* bs = B + (long)(kc + bk) * N + bn + bn4;
            uint32_t bd = bbase + (nxt * 16 * TBP + bk * TBP + bn4) * 4;
            CP_ASYNC16(bd, bs);
            CP_COMMIT();
        }

        #pragma unroll
        for (int k8 = 0; k8 < 16; k8 += 8) {
            uint32_t ah[2][4], al[2][4];
            #pragma unroll
            for (int mt = 0; mt < 2; mt++) {
                int r0 = warpM * 32 + mt * 16 + gr;
                float v0 = As[cur][r0    ][k8 + gc];
                float v1 = As[cur][r0 + 8][k8 + gc];
                float v2 = As[cur][r0    ][k8 + gc + 4];
                float v3 = As[cur][r0 + 8][k8 + gc + 4];
                if (EXACT) {
                    f2tf32x2(v0, ah[mt][0], al[mt][0]);
                    f2tf32x2(v1, ah[mt][1], al[mt][1]);
                    f2tf32x2(v2, ah[mt][2], al[mt][2]);
                    f2tf32x2(v3, ah[mt][3], al[mt][3]);
                } else {
                    ah[mt][0] = f2tf32(v0); ah[mt][1] = f2tf32(v1);
                    ah[mt][2] = f2tf32(v2); ah[mt][3] = f2tf32(v3);
                }
            }
            uint32_t bh[NT][2], bl[NT][2];
            #pragma unroll
            for (int nt = 0; nt < NT; nt++) {
                int n = warpN * (NT * 8) + nt * 8 + gr;
                float v0 = Bs[cur][k8 + gc    ][n];
                float v1 = Bs[cur][k8 + gc + 4][n];
                if (EXACT) {
                    f2tf32x2(v0, bh[nt][0], bl[nt][0]);
                    f2tf32x2(v1, bh[nt][1], bl[nt][1]);
                } else {
                    bh[nt][0] = f2tf32(v0); bh[nt][1] = f2tf32(v1);
                }
            }
            #pragma unroll
            for (int mt = 0; mt < 2; mt++)
                #pragma unroll
                for (int nt = 0; nt < NT; nt++) {
                    if (EXACT) {
                        mma_tf32(c[mt][nt], al[mt], bh[nt]);
                        mma_tf32(c[mt][nt], ah[mt], bl[nt]);
                    }
                    mma_tf32(c[mt][nt], ah[mt], bh[nt]);
                }
        }
    }

    #pragma unroll
    for (int mt = 0; mt < 2; mt++) {
        #pragma unroll
        for (int nt = 0; nt < NT; nt++) {
            int row0 = bm + warpM * 32 + mt * 16 + gr;
            int col  = bn + warpN * (NT * 8) + nt * 8 + gc * 2;
            long o0 = coff + (long)row0 * N + col;
            long o1 = coff + (long)(row0 + 8) * N + col;
            float2 v0 = make_float2(c[mt][nt][0], c[mt][nt][1]);
            float2 v1 = make_float2(c[mt][nt][2], c[mt][nt][3]);
            if (OMODE == 1) {
                float h0 = __bfloat162float(__float2bfloat16(v0.x));
                float h1 = __bfloat162float(__float2bfloat16(v0.y));
                float h2 = __bfloat162float(__float2bfloat16(v1.x));
                float h3 = __bfloat162float(__float2bfloat16(v1.y));
                ((uint32_t*)outH)[o0 >> 1] = pack_bf16x2(h0, h1);
                ((uint32_t*)outH)[o1 >> 1] = pack_bf16x2(h2, h3);
                ((uint32_t*)outL)[o0 >> 1] = pack_bf16x2(v0.x - h0, v0.y - h1);
                ((uint32_t*)outL)[o1 >> 1] = pack_bf16x2(v1.x - h2, v1.y - h3);
            } else if (OMODE == 3) {
                if (bz == 0) {
                    *(float2*)(C + o0) = v0;
                    *(float2*)(C + o1) = v1;
                } else {
                    ((uint32_t*)outH)[o0 >> 1] = pack_bf16x2(v0.x, v0.y);
                    ((uint32_t*)outH)[o1 >> 1] = pack_bf16x2(v1.x, v1.y);
                }
            } else {
                if (Cadd) {
                    float2 w0 = *(const float2*)(Cadd + o0);
                    float2 w1 = *(const float2*)(Cadd + o1);
                    v0.x += w0.x; v0.y += w0.y;
                    v1.x += w1.x; v1.y += w1.y;
                }
                *(float2*)(C + o0) = v0;
                *(float2*)(C + o1) = v1;
            }
        }
    }
}

// ============================================================================
// split-bf16 GEMM for y = t @ gw[li]. BM=64, BN=64, BK=32; 192 CTAs.
// ============================================================================
#define TGP 80
#define TGB 5120

__global__ __launch_bounds__(256, 4)
void gemm_tgw(const __nv_bfloat16* __restrict__ tH, const __nv_bfloat16* __restrict__ tL,
              const uint2* __restrict__ gwfH, const uint2* __restrict__ gwfL,
              int li, float* __restrict__ y)
{
    __shared__ __align__(16) char smem[2 * 2 * TGB];
    const uint32_t sbase = smem_to_u32(smem);
    const int tid  = threadIdx.x;
    const int lane = tid & 31;
    const int wid  = tid >> 5;
    const int warpM = wid >> 2;
    const int warpN = wid & 3;
    const int bm = blockIdx.y * 64;
    const int bn = blockIdx.x * 64;

    const int srow = tid >> 2;
    const int spart = tid & 3;

    {
        uint32_t d = sbase + srow * TGP + spart * 16;
        CP_ASYNC16(d, tH + (long)(bm + srow) * DDIM + spart * 8);
        CP_ASYNC16(d + TGB, tL + (long)(bm + srow) * DDIM + spart * 8);
        CP_COMMIT();
    }

    float c[2][2][4];
    #pragma unroll
    for (int mt = 0; mt < 2; mt++)
        #pragma unroll
        for (int nt = 0; nt < 2; nt++)
            #pragma unroll
            for (int q = 0; q < 4; q++) c[mt][nt][q] = 0.f;

    const long nnb = (long)li * 96 + blockIdx.x * 8 + warpN * 2;

    for (int kc = 0; kc < 24; kc++) {
        CP_WAIT0();
        __syncthreads();
        const int cur = kc & 1;
        if (kc < 23) {
            const int k0 = (kc + 1) * 32;
            uint32_t d = sbase + (cur ^ 1) * 2 * TGB + srow * TGP + spart * 16;
            CP_ASYNC16(d, tH + (long)(bm + srow) * DDIM + k0 + spart * 8);
            CP_ASYNC16(d + TGB, tL + (long)(bm + srow) * DDIM + k0 + spart * 8);
            CP_COMMIT();
        }

        #pragma unroll
        for (int ks = 0; ks < 2; ks++) {
            const int kkg = kc * 2 + ks;
            uint32_t bh[2][2], bl[2][2];
            #pragma unroll
            for (int nt = 0; nt < 2; nt++) {
                uint2 v = gwfH[((nnb + nt) * 48 + kkg) * 32 + lane];
                bh[nt][0] = v.x; bh[nt][1] = v.y;
                v = gwfL[((nnb + nt) * 48 + kkg) * 32 + lane];
                bl[nt][0] = v.x; bl[nt][1] = v.y;
            }
            #pragma unroll
            for (int mt = 0; mt < 2; mt++) {
                uint32_t addr = sbase + cur * 2 * TGB +
                    (warpM * 32 + mt * 16 + (lane & 15)) * TGP +
                    (lane >> 4) * 16 + ks * 32;
                uint32_t ahf[4], alf[4];
                ldsm_x4(ahf[0], ahf[1], ahf[2], ahf[3], addr);
                ldsm_x4(alf[0], alf[1], alf[2], alf[3], addr + TGB);
                #pragma unroll
                for (int nt = 0; nt < 2; nt++) {
                    mma_bf16(c[mt][nt], ahf, bh[nt]);
                    mma_bf16(c[mt][nt], alf, bh[nt]);
                    mma_bf16(c[mt][nt], ahf, bl[nt]);
                }
            }
        }
    }

    const int gr = lane >> 2;
    const int gc = lane & 3;
    #pragma unroll
    for (int mt = 0; mt < 2; mt++)
        #pragma unroll
        for (int nt = 0; nt < 2; nt++) {
            int row0 = bm + warpM * 32 + mt * 16 + gr;
            int col  = bn + warpN * 16 + nt * 8 + gc * 2;
            *(float2*)(y + (long)row0 * DDIM + col) =
                make_float2(c[mt][nt][0], c[mt][nt][1]);
            *(float2*)(y + (long)(row0 + 8) * DDIM + col) =
                make_float2(c[mt][nt][2], c[mt][nt][3]);
        }
}

// ============================================================================
// Coalesced fragment prep (smem-staged transpose).
// ============================================================================
template <bool SPLIT>
__global__ void prep_frag(const float* __restrict__ src, int srcN, long srcStride,
                          int nnPerZ, uint2* __restrict__ dstH, uint2* __restrict__ dstL)
{
    __shared__ float tile[16][68];
    const int tid = threadIdx.x;
    const float* S = src + (long)blockIdx.z * srcStride;

    {
        int row = tid >> 4;
        int col4 = (tid & 15) * 4;
        float4 v = *(const float4*)(S + (long)(blockIdx.y * 16 + row) * srcN
                                    + blockIdx.x * 64 + col4);
        tile[row][col4 + 0] = v.x;
        tile[row][col4 + 1] = v.y;
        tile[row][col4 + 2] = v.z;
        tile[row][col4 + 3] = v.w;
    }
    __syncthreads();

    const int nn_local = tid >> 5;
    const int lane = tid & 31;
    const int n_l = nn_local * 8 + (lane >> 2);
    const int r0 = 2 * (lane & 3);
    float g0 = tile[r0][n_l],     g1 = tile[r0 + 1][n_l];
    float g2 = tile[r0 + 8][n_l], g3 = tile[r0 + 9][n_l];

    long nnG = (long)blockIdx.z * nnPerZ + blockIdx.x * 8 + nn_local;
    long idx = (nnG * 48 + blockIdx.y) * 32 + lane;

    if (SPLIT) {
        float h0 = __bfloat162float(__float2bfloat16(g0));
        float h1 = __bfloat162float(__float2bfloat16(g1));
        float h2 = __bfloat162float(__float2bfloat16(g2));
        float h3 = __bfloat162float(__float2bfloat16(g3));
        uint2 H, L;
        H.x = pack_bf16x2(h0, h1);           H.y = pack_bf16x2(h2, h3);
        L.x = pack_bf16x2(g0 - h0, g1 - h1); L.y = pack_bf16x2(g2 - h2, g3 - h3);
        dstH[idx] = H;
        dstL[idx] = L;
    } else {
        uint2 H;
        H.x = pack_bf16x2(g0, g1);
        H.y = pack_bf16x2(g2, g3);
        dstH[idx] = H;
    }
}

// ============================================================================
// Fused edge-MLP via mma.sync bf16 (proven R7/R10 version). One CTA/(b,i).
// fp32 hib A-build; B frags from global; double-buffered A; 2 CTAs/SM.
// ============================================================================
#define APITCH 144
#define ABUF   18432
#define SM_A     0
#define SM_HIB   36864
#define SM_B2    39936
#define SM_W3    41472
#define SM_SCAL  43008
#define SM_RED   43520
#define SM_TOTAL 43584

__global__ __launch_bounds__(256, 2)
void edge_mma_kernel(const float* __restrict__ hi, const __nv_bfloat16* __restrict__ hj2,
                     const float* __restrict__ adj, const float* __restrict__ b1,
                     const uint2* __restrict__ bfrag, const float* __restrict__ b2,
                     const float* __restrict__ w3, const float* __restrict__ b3p,
                     float* __restrict__ a_out, float* __restrict__ denom_out)
{
    __shared__ __align__(16) char smem[SM_TOTAL];
    const uint32_t sbase = smem_to_u32(smem);
    const int tid  = threadIdx.x;
    const int lane = tid & 31;
    const int wid  = tid >> 5;
    const int warpM = wid >> 2;
    const int warpN = wid & 3;
    const int bi = blockIdx.x;
    const int b  = bi >> 7;
    const int i  = bi & 127;

    float* hib  = (float*)(smem + SM_HIB);
    float* b2s  = (float*)(smem + SM_B2);
    float* w3s  = (float*)(smem + SM_W3);
    float* scal = (float*)(smem + SM_SCAL);
    float* red  = (float*)(smem + SM_RED);

    for (int k = tid; k < DDIM; k += 256) hib[k] = hi[(long)bi * DDIM + k] + b1[k];
    for (int k = tid; k < 384; k += 256) { b2s[k] = b2[k]; w3s[k] = w3[k]; }
    if (tid < 128) scal[tid] = 0.f;
    __syncthreads();

    const int aj = tid >> 1;
    const int ahh = tid & 1;
    const __nv_bfloat16* hjrow = hj2 + ((long)b * LSEQ + aj) * DDIM + ahh * 32;
    char* abase_th = smem + SM_A + aj * APITCH + ahh * 64;

    for (int nc = 0; nc < 3; nc++) {
        float c[4][4][4];
        #pragma unroll
        for (int mt = 0; mt < 4; mt++)
            #pragma unroll
            for (int nt = 0; nt < 4; nt++)
                #pragma unroll
                for (int q = 0; q < 4; q++) c[mt][nt][q] = 0.f;

        const uint2* bb = bfrag + ((long)(nc * 16 + warpN * 4) * 48) * 32 + lane;

        {
            const uint4* src = (const uint4*)hjrow;
            const float* hb  = hib + ahh * 32;
            #pragma unroll
            for (int s = 0; s < 4; s++) {
                uint4 v = src[s];
                __nv_bfloat162* p = (__nv_bfloat162*)&v;
                uint4 o;
                uint32_t* po = (uint32_t*)&o;
                #pragma unroll
                for (int h = 0; h < 4; h++) {
                    float2 f = __bfloat1622float2(p[h]);
                    po[h] = pack_bf16x2(fmaxf(f.x + hb[s * 8 + h * 2], 0.f),
                                        fmaxf(f.y + hb[s * 8 + h * 2 + 1], 0.f));
                }
                *(uint4*)(abase_th + s * 16) = o;
            }
        }
        __syncthreads();

        for (int kc = 0; kc < 12; kc++) {
            const int cur = kc & 1;

            uint32_t bfr[4][4][2];
            #pragma unroll
            for (int nt = 0; nt < 4; nt++)
                #pragma unroll
                for (int ks = 0; ks < 4; ks++) {
                    uint2 v = bb[((long)nt * 48 + kc * 4 + ks) * 32];
                    bfr[nt][ks][0] = v.x;
                    bfr[nt][ks][1] = v.y;
                }

            if (kc < 11) {
                const int k0 = (kc + 1) * 64;
                const uint4* src = (const uint4*)(hjrow + k0);
                const float* hb  = hib + k0 + ahh * 32;
                char* ab = abase_th + (cur ^ 1) * ABUF;
                #pragma unroll
                for (int s = 0; s < 4; s++) {
                    uint4 v = src[s];
                    __nv_bfloat162* p = (__nv_bfloat162*)&v;
                    uint4 o;
                    uint32_t* po = (uint32_t*)&o;
                    #pragma unroll
                    for (int h = 0; h < 4; h++) {
                        float2 f = __bfloat1622float2(p[h]);
                        po[h] = pack_bf16x2(fmaxf(f.x + hb[s * 8 + h * 2], 0.f),
                                            fmaxf(f.y + hb[s * 8 + h * 2 + 1], 0.f));
                    }
                    *(uint4*)(ab + s * 16) = o;
                }
            }

            const uint32_t abase = sbase + SM_A + cur * ABUF;
            #pragma unroll
            for (int ks = 0; ks < 4; ks++) {
                uint32_t afr[4][4];
                #pragma unroll
                for (int mt = 0; mt < 4; mt++) {
                    uint32_t addr = abase +
                        (warpM * 64 + mt * 16 + (lane & 15)) * APITCH +
                        (ks * 16 + (lane >> 4) * 8) * 2;
                    ldsm_x4(afr[mt][0], afr[mt][1], afr[mt][2], afr[mt][3], addr);
                }
                #pragma unroll
                for (int mt = 0; mt < 4; mt++)
                    #pragma unroll
                    for (int nt = 0; nt < 4; nt++)
                        mma_bf16(c[mt][nt], afr[mt], bfr[nt][ks]);
            }
            __syncthreads();
        }

        const int qr = lane >> 2;
        const int qc = lane & 3;
        #pragma unroll
        for (int mt = 0; mt < 4; mt++) {
            float p0 = 0.f, p1 = 0.f;
            #pragma unroll
            for (int nt = 0; nt < 4; nt++) {
                int n0 = nc * 128 + warpN * 32 + nt * 8 + qc * 2;
                float bw0 = b2s[n0], bw1 = b2s[n0 + 1];
                float ww0 = w3s[n0], ww1 = w3s[n0 + 1];
                p0 += fmaxf(c[mt][nt][0] + bw0, 0.f) * ww0
                    + fmaxf(c[mt][nt][1] + bw1, 0.f) * ww1;
                p1 += fmaxf(c[mt][nt][2] + bw0, 0.f) * ww0
                    + fmaxf(c[mt][nt][3] + bw1, 0.f) * ww1;
            }
            p0 += __shfl_xor_sync(0xffffffffu, p0, 1);
            p0 += __shfl_xor_sync(0xffffffffu, p0, 2);
            p1 += __shfl_xor_sync(0xffffffffu, p1, 1);
            p1 += __shfl_xor_sync(0xffffffffu, p1, 2);
            if (qc == 0) {
                atomicAdd(&scal[warpM * 64 + mt * 16 + qr], p0);
                atomicAdd(&scal[warpM * 64 + mt * 16 + qr + 8], p1);
            }
        }
        __syncthreads();
    }

    if (tid < 128) {
        float x  = scal[tid] + b3p[0];
        float ew = 1.f / (1.f + expf(-x));
        scal[tid] = adj[(long)bi * 128 + tid] * ew + (tid == i ? 1.f : 0.f);
    }
    __syncthreads();
    if (tid < 32) {
        float m = fmaxf(fmaxf(scal[tid], scal[tid + 32]),
                        fmaxf(scal[tid + 64], scal[tid + 96]));
        for (int sh = 16; sh; sh >>= 1) m = fmaxf(m, __shfl_xor_sync(0xffffffffu, m, sh));
        if (tid == 0) red[0] = m;
    }
    __syncthreads();
    if (tid < 128) scal[tid] = expf(scal[tid] - red[0]);
    __syncthreads();
    if (tid < 32) {
        float s = scal[tid] + scal[tid + 32] + scal[tid + 64] + scal[tid + 96];
        for (int sh = 16; sh; sh >>= 1) s += __shfl_xor_sync(0xffffffffu, s, sh);
        if (tid == 0) red[1] = s;
    }
    __syncthreads();
    if (tid < 128) {
        float p = scal[tid] / red[1];
        a_out[(long)bi * 128 + tid] = p + (tid == i ? 1.f : 0.f);
        scal[tid] = p;
    }
    __syncthreads();
    if (tid < 32) {
        float s = scal[tid] + scal[tid + 32] + scal[tid + 64] + scal[tid + 96];
        for (int sh = 16; sh; sh >>= 1) s += __shfl_xor_sync(0xffffffffu, s, sh);
        if (tid == 0) denom_out[bi] = 1.f + s;
    }
}

// ---------------- fused bias + denom + relu + LayerNorm ----------------------
__global__ __launch_bounds__(256)
void ln_kernel(const float* __restrict__ y, const float* __restrict__ gb,
               const float* __restrict__ lng, const float* __restrict__ lnb,
               const float* __restrict__ denom, float* __restrict__ outp)
{
    const int row = blockIdx.x;
    const int tid = threadIdx.x;
    const float inv = 1.f / denom[row];
    const float* yr = y + (long)row * DDIM;

    float v[3];
    float s = 0.f, sq = 0.f;
    #pragma unroll
    for (int p = 0; p < 3; p++) {
        int n = tid + p * 256;
        float x = fmaxf((yr[n] + 2.f * gb[n]) * inv, 0.f);
        v[p] = x; s += x; sq += x * x;
    }
    __shared__ float rs[8], rq[8], mm[2];
    for (int sh = 16; sh; sh >>= 1) {
        s  += __shfl_xor_sync(0xffffffffu, s,  sh);
        sq += __shfl_xor_sync(0xffffffffu, sq, sh);
    }
    if ((tid & 31) == 0) { rs[tid >> 5] = s; rq[tid >> 5] = sq; }
    __syncthreads();
    if (tid == 0) {
        float S = 0.f, Q = 0.f;
        #pragma unroll
        for (int q = 0; q < 8; q++) { S += rs[q]; Q += rq[q]; }
        float mean = S / (float)DDIM;
        float var  = Q / (float)DDIM - mean * mean;
        mm[0] = mean;
        mm[1] = rsqrtf(var + 1e-5f);
    }
    __syncthreads();
    const float mean = mm[0], rstd = mm[1];
    float* orow = outp + (long)row * DDIM;
    #pragma unroll
    for (int p = 0; p < 3; p++) {
        int n = tid + p * 256;
        orow[n] = (v[p] - mean) * rstd * lng[n] + lnb[n];
    }
}

// ---------------- zero mask tail ---------------------------------------------
__global__ void zero_tail_kernel(float* __restrict__ dst, int start, int total)
{
    int idx = start + blockIdx.x * 256 + threadIdx.x;
    if (idx < total) dst[idx] = 0.f;
}

// ---------------- launch ------------------------------------------------------
extern "C" void kernel_launch(void* const* d_in, const int* in_sizes, int n_in,
                              void* d_out, int out_size)
{
    const float* adj    = (const float*)d_in[0];
    const float* inputs = (const float*)d_in[1];
    const float* w1     = (const float*)d_in[2];
    const float* b1     = (const float*)d_in[3];
    const float* w2     = (const float*)d_in[4];
    const float* b2     = (const float*)d_in[5];
    const float* w3     = (const float*)d_in[6];
    const float* b3     = (const float*)d_in[7];
    const float* gw     = (const float*)d_in[8];
    const float* gb     = (const float*)d_in[9];
    const float* lng    = (const float*)d_in[10];
    const float* lnb    = (const float*)d_in[11];

    float *hi, *a, *denom, *y, *buf;
    __nv_bfloat16 *hj2, *tH, *tL;
    uint2 *bfrag, *gwfH, *gwfL;
    cudaGetSymbolAddress((void**)&hi,    g_hi);
    cudaGetSymbolAddress((void**)&a,     g_a);
    cudaGetSymbolAddress((void**)&denom, g_denom);
    cudaGetSymbolAddress((void**)&y,     g_y);
    cudaGetSymbolAddress((void**)&buf,   g_buf);
    cudaGetSymbolAddress((void**)&hj2,   g_hj2);
    cudaGetSymbolAddress((void**)&tH,    g_tH);
    cudaGetSymbolAddress((void**)&tL,    g_tL);
    cudaGetSymbolAddress((void**)&bfrag, g_bfrag);
    cudaGetSymbolAddress((void**)&gwfH,  g_gwfH);
    cudaGetSymbolAddress((void**)&gwfL,  g_gwfL);

    dim3 blk(256);

    // w2 fragments first (edge needs them), then hi/hj GEMM, then gw fragments
    // (only needed after the edge kernel).
    prep_frag<false><<<dim3(6, 48, 1), blk>>>(w2, 384, 0L, 0, bfrag, nullptr);

    // hi = X @ w1[:768] (fp32), hj = X @ w1[768:] (bf16, direct) — ONE 192-CTA launch
    gemm_tf32<128, false, 3><<<dim3(12, 8, 2), blk>>>(
        inputs, w1, hi, nullptr, hj2, nullptr,
        ROWS, DDIM, DDIM, 0L, (long)DDIM * DDIM, 0L);

    prep_frag<true><<<dim3(12, 48, 3), blk>>>(gw, DDIM, (long)DDIM * DDIM, 96,
                                              gwfH, gwfL);

    // fused edge MLP (bf16 tensor cores) + softmax -> a (= softmax + I), denom
    edge_mma_kernel<<<1024, blk>>>(hi, hj2, adj, b1, bfrag, b2, w3, b3, a, denom);

    const float* cur = inputs;
    for (int li = 0; li < 3; li++) {
        // t = (a + I) @ cur  (3xTF32 exact; epilogue emits bf16 hi/lo); 192 CTAs
        gemm_tf32<64, true, 1><<<dim3(12, 2, NBATCH), blk>>>(
            a, cur, nullptr, nullptr, tH, tL,
            LSEQ, DDIM, LSEQ,
            (long)LSEQ * LSEQ, (long)LSEQ * DDIM, (long)LSEQ * DDIM);
        // y = t @ gw[li]  (split-bf16 exact); 192 CTAs
        gemm_tgw<<<dim3(12, 16), blk>>>(tH, tL, gwfH, gwfL, li, y);
        float* nxt = (li == 2) ? (float*)d_out
                               : buf + (long)(li & 1) * ROWS * DDIM;
        ln_kernel<<<1024, blk>>>(y, gb + li * DDIM, lng + li * DDIM, lnb + li * DDIM,
                                 denom, nxt);
        cur = nxt;
    }

    int tail = out_size - ROWS * DDIM;
    if (tail > 0)
        zero_tail_kernel<<<(tail + 255) / 256, blk>>>((float*)d_out, ROWS * DDIM, out_size);
}

// round 15
// speedup vs baseline: 1.6891x; 1.0849x over previous
#include <cuda_runtime.h>
#include <cuda_bf16.h>
#include <cstdint>

#define LSEQ 128
#define DDIM 768
#define NBATCH 8
#define ROWS (NBATCH * LSEQ)   // 1024

// ---------------- scratch (__device__ globals; no allocation) ----------------
__device__ float g_hi[ROWS * DDIM];      // hi (fp32)
__device__ float g_a[NBATCH * LSEQ * LSEQ];
__device__ float g_denom[ROWS];
__device__ float g_y[ROWS * DDIM];
__device__ float g_buf[2][ROWS * DDIM];
__device__ __align__(16) __nv_bfloat16 g_hj2[ROWS * DDIM];  // hj bf16 (direct from GEMM)
__device__ __align__(16) __nv_bfloat16 g_tH[ROWS * DDIM];   // t split hi
__device__ __align__(16) __nv_bfloat16 g_tL[ROWS * DDIM];   // t split lo
// w2 fragments (m16n8k16 B order): [nn 0..47][kk 0..47][lane]
__device__ __align__(16) uint2 g_bfrag[48 * 48 * 32];
// gw split-bf16 fragments: [li*96 + nn][kk 0..47][lane]
__device__ __align__(16) uint2 g_gwfH[3 * 96 * 48 * 32];
__device__ __align__(16) uint2 g_gwfL[3 * 96 * 48 * 32];

// ============================================================================
// PTX helpers (baseline features only)
// ============================================================================
__device__ __forceinline__ uint32_t smem_to_u32(const void* p) {
    uint32_t a;
    asm("{ .reg .u64 t; cvta.to.shared.u64 t, %1; cvt.u32.u64 %0, t; }" : "=r"(a) : "l"(p));
    return a;
}
#define CP_ASYNC16(dst, src) \
    asm volatile("cp.async.cg.shared.global [%0], [%1], 16;" :: "r"(dst), "l"(src))
#define CP_COMMIT() asm volatile("cp.async.commit_group;" ::: "memory")
#define CP_WAIT0()  asm volatile("cp.async.wait_group 0;" ::: "memory")

__device__ __forceinline__ void ldsm_x4(uint32_t& r0, uint32_t& r1, uint32_t& r2,
                                        uint32_t& r3, uint32_t addr) {
    asm volatile("ldmatrix.sync.aligned.m8n8.x4.shared.b16 {%0,%1,%2,%3}, [%4];"
                 : "=r"(r0), "=r"(r1), "=r"(r2), "=r"(r3) : "r"(addr));
}
__device__ __forceinline__ void mma_bf16(float* c, const uint32_t* a, const uint32_t* b) {
    asm volatile("mma.sync.aligned.m16n8k16.row.col.f32.bf16.bf16.f32 "
                 "{%0,%1,%2,%3}, {%4,%5,%6,%7}, {%8,%9}, {%0,%1,%2,%3};"
                 : "+f"(c[0]), "+f"(c[1]), "+f"(c[2]), "+f"(c[3])
                 : "r"(a[0]), "r"(a[1]), "r"(a[2]), "r"(a[3]), "r"(b[0]), "r"(b[1]));
}
__device__ __forceinline__ void mma_tf32(float* c, const uint32_t* a, const uint32_t* b) {
    asm volatile("mma.sync.aligned.m16n8k8.row.col.f32.tf32.tf32.f32 "
                 "{%0,%1,%2,%3}, {%4,%5,%6,%7}, {%8,%9}, {%0,%1,%2,%3};"
                 : "+f"(c[0]), "+f"(c[1]), "+f"(c[2]), "+f"(c[3])
                 : "r"(a[0]), "r"(a[1]), "r"(a[2]), "r"(a[3]), "r"(b[0]), "r"(b[1]));
}
__device__ __forceinline__ uint32_t f2tf32(float x) {
    uint32_t r;
    asm("cvt.rna.tf32.f32 %0, %1;" : "=r"(r) : "f"(x));
    return r;
}
__device__ __forceinline__ void f2tf32x2(float x, uint32_t& hi, uint32_t& lo) {
    hi = f2tf32(x);
    lo = f2tf32(x - __uint_as_float(hi));
}
__device__ __forceinline__ uint32_t pack_bf16x2(float a, float b) {
    __nv_bfloat162 r = __floats2bfloat162_rn(a, b);
    return *(uint32_t*)&r;
}

// ============================================================================
// tf32 tensor GEMM: row-major. BM x 64 x BK=16 tiles.
// BM=128: 8 warps 4Mx2N. BM=64: 8 warps 2Mx4N.
// EXACT: 3xTF32.
// OMODE: 0 = fp32 C (+Cadd) | 1 = bf16 hi/lo split | 3 = dual: z=0 fp32 C,
//        z=1 bf16 outH (hi/hj fused launch; sC must be 0 so coff==0).
// ============================================================================
#define TAP 20
#define TBP 72

template <int BM, bool EXACT, int OMODE>
__global__ __launch_bounds__(256)
void gemm_tf32(const float* __restrict__ A, const float* __restrict__ B,
               float* __restrict__ C, const float* __restrict__ Cadd,
               __nv_bfloat16* __restrict__ outH, __nv_bfloat16* __restrict__ outL,
               int M, int N, int K, long sA, long sB, long sC)
{
    constexpr int WN = (BM == 128) ? 2 : 4;
    constexpr int NT = (BM == 128) ? 4 : 2;

    const int bz = blockIdx.z;
    A += (long)bz * sA;
    B += (long)bz * sB;
    const long coff = (long)bz * sC;

    const int bm = blockIdx.y * BM;
    const int bn = blockIdx.x * 64;

    __shared__ float As[2][BM][TAP];
    __shared__ float Bs[2][16][TBP];

    const int tid  = threadIdx.x;
    const int lane = tid & 31;
    const int wid  = tid >> 5;
    const int warpM = wid / WN;
    const int warpN = wid % WN;
    const int gr = lane >> 2;
    const int gc = lane & 3;

    const uint32_t sbase = smem_to_u32(&As[0][0][0]);
    const uint32_t bbase = smem_to_u32(&Bs[0][0][0]);

    const int arow = (BM == 128) ? (tid >> 1) : (tid >> 2);
    const int akq  = (BM == 128) ? ((tid & 1) * 8) : ((tid & 3) * 4);
    const int bk   = tid >> 4;
    const int bn4  = (tid & 15) * 4;

    const int nK = K >> 4;

    {
        const float* as = A + (long)(bm + arow) * K + akq;
        uint32_t ad = sbase + (arow * TAP + akq) * 4;
        CP_ASYNC16(ad, as);
        if (BM == 128) CP_ASYNC16(ad + 16, as + 4);
        const float* bs = B + (long)bk * N + bn + bn4;
        uint32_t bd = bbase + (bk * TBP + bn4) * 4;
        CP_ASYNC16(bd, bs);
        CP_COMMIT();
    }

    float c[2][NT][4];
    #pragma unroll
    for (int mt = 0; mt < 2; mt++)
        #pragma unroll
        for (int nt = 0; nt < NT; nt++)
            #pragma unroll
            for (int q = 0; q < 4; q++) c[mt][nt][q] = 0.f;

    for (int ki = 0; ki < nK; ki++) {
        CP_WAIT0();
        __syncthreads();
        const int cur = ki & 1;
        if (ki + 1 < nK) {
            const int nxt = cur ^ 1;
            const int kc = (ki + 1) * 16;
            const float* as = A + (long)(bm + arow) * K + kc + akq;
            uint32_t ad = sbase + (nxt * BM * TAP + arow * TAP + akq) * 4;
            CP_ASYNC16(ad, as);
            if (BM == 128) CP_ASYNC16(ad + 16, as + 4);
            const float* bs = B + (long)(kc + bk) * N + bn + bn4;
            uint32_t bd = bbase + (nxt * 16 * TBP + bk * TBP + bn4) * 4;
            CP_ASYNC16(bd, bs);
            CP_COMMIT();
        }

        #pragma unroll
        for (int k8 = 0; k8 < 16; k8 += 8) {
            uint32_t ah[2][4], al[2][4];
            #pragma unroll
            for (int mt = 0; mt < 2; mt++) {
                int r0 = warpM * 32 + mt * 16 + gr;
                float v0 = As[cur][r0    ][k8 + gc];
                float v1 = As[cur][r0 + 8][k8 + gc];
                float v2 = As[cur][r0    ][k8 + gc + 4];
                float v3 = As[cur][r0 + 8][k8 + gc + 4];
                if (EXACT) {
                    f2tf32x2(v0, ah[mt][0], al[mt][0]);
                    f2tf32x2(v1, ah[mt][1], al[mt][1]);
                    f2tf32x2(v2, ah[mt][2], al[mt][2]);
                    f2tf32x2(v3, ah[mt][3], al[mt][3]);
                } else {
                    ah[mt][0] = f2tf32(v0); ah[mt][1] = f2tf32(v1);
                    ah[mt][2] = f2tf32(v2); ah[mt][3] = f2tf32(v3);
                }
            }
            uint32_t bh[NT][2], bl[NT][2];
            #pragma unroll
            for (int nt = 0; nt < NT; nt++) {
                int n = warpN * (NT * 8) + nt * 8 + gr;
                float v0 = Bs[cur][k8 + gc    ][n];
                float v1 = Bs[cur][k8 + gc + 4][n];
                if (EXACT) {
                    f2tf32x2(v0, bh[nt][0], bl[nt][0]);
                    f2tf32x2(v1, bh[nt][1], bl[nt][1]);
                } else {
                    bh[nt][0] = f2tf32(v0); bh[nt][1] = f2tf32(v1);
                }
            }
            #pragma unroll
            for (int mt = 0; mt < 2; mt++)
                #pragma unroll
                for (int nt = 0; nt < NT; nt++) {
                    if (EXACT) {
                        mma_tf32(c[mt][nt], al[mt], bh[nt]);
                        mma_tf32(c[mt][nt], ah[mt], bl[nt]);
                    }
                    mma_tf32(c[mt][nt], ah[mt], bh[nt]);
                }
        }
    }

    #pragma unroll
    for (int mt = 0; mt < 2; mt++) {
        #pragma unroll
        for (int nt = 0; nt < NT; nt++) {
            int row0 = bm + warpM * 32 + mt * 16 + gr;
            int col  = bn + warpN * (NT * 8) + nt * 8 + gc * 2;
            long o0 = coff + (long)row0 * N + col;
            long o1 = coff + (long)(row0 + 8) * N + col;
            float2 v0 = make_float2(c[mt][nt][0], c[mt][nt][1]);
            float2 v1 = make_float2(c[mt][nt][2], c[mt][nt][3]);
            if (OMODE == 1) {
                float h0 = __bfloat162float(__float2bfloat16(v0.x));
                float h1 = __bfloat162float(__float2bfloat16(v0.y));
                float h2 = __bfloat162float(__float2bfloat16(v1.x));
                float h3 = __bfloat162float(__float2bfloat16(v1.y));
                ((uint32_t*)outH)[o0 >> 1] = pack_bf16x2(h0, h1);
                ((uint32_t*)outH)[o1 >> 1] = pack_bf16x2(h2, h3);
                ((uint32_t*)outL)[o0 >> 1] = pack_bf16x2(v0.x - h0, v0.y - h1);
                ((uint32_t*)outL)[o1 >> 1] = pack_bf16x2(v1.x - h2, v1.y - h3);
            } else if (OMODE == 3) {
                if (bz == 0) {
                    *(float2*)(C + o0) = v0;
                    *(float2*)(C + o1) = v1;
                } else {
                    ((uint32_t*)outH)[o0 >> 1] = pack_bf16x2(v0.x, v0.y);
                    ((uint32_t*)outH)[o1 >> 1] = pack_bf16x2(v1.x, v1.y);
                }
            } else {
                if (Cadd) {
                    float2 w0 = *(const float2*)(Cadd + o0);
                    float2 w1 = *(const float2*)(Cadd + o1);
                    v0.x += w0.x; v0.y += w0.y;
                    v1.x += w1.x; v1.y += w1.y;
                }
                *(float2*)(C + o0) = v0;
                *(float2*)(C + o1) = v1;
            }
        }
    }
}

// ============================================================================
// split-bf16 GEMM for y = t @ gw[li]. BM=64, BN=64, BK=32; 192 CTAs.
// ============================================================================
#define TGP 80
#define TGB 5120

__global__ __launch_bounds__(256, 4)
void gemm_tgw(const __nv_bfloat16* __restrict__ tH, const __nv_bfloat16* __restrict__ tL,
              const uint2* __restrict__ gwfH, const uint2* __restrict__ gwfL,
              int li, float* __restrict__ y)
{
    __shared__ __align__(16) char smem[2 * 2 * TGB];
    const uint32_t sbase = smem_to_u32(smem);
    const int tid  = threadIdx.x;
    const int lane = tid & 31;
    const int wid  = tid >> 5;
    const int warpM = wid >> 2;
    const int warpN = wid & 3;
    const int bm = blockIdx.y * 64;
    const int bn = blockIdx.x * 64;

    const int srow = tid >> 2;
    const int spart = tid & 3;

    {
        uint32_t d = sbase + srow * TGP + spart * 16;
        CP_ASYNC16(d, tH + (long)(bm + srow) * DDIM + spart * 8);
        CP_ASYNC16(d + TGB, tL + (long)(bm + srow) * DDIM + spart * 8);
        CP_COMMIT();
    }

    float c[2][2][4];
    #pragma unroll
    for (int mt = 0; mt < 2; mt++)
        #pragma unroll
        for (int nt = 0; nt < 2; nt++)
            #pragma unroll
            for (int q = 0; q < 4; q++) c[mt][nt][q] = 0.f;

    const long nnb = (long)li * 96 + blockIdx.x * 8 + warpN * 2;

    for (int kc = 0; kc < 24; kc++) {
        CP_WAIT0();
        __syncthreads();
        const int cur = kc & 1;
        if (kc < 23) {
            const int k0 = (kc + 1) * 32;
            uint32_t d = sbase + (cur ^ 1) * 2 * TGB + srow * TGP + spart * 16;
            CP_ASYNC16(d, tH + (long)(bm + srow) * DDIM + k0 + spart * 8);
            CP_ASYNC16(d + TGB, tL + (long)(bm + srow) * DDIM + k0 + spart * 8);
            CP_COMMIT();
        }

        #pragma unroll
        for (int ks = 0; ks < 2; ks++) {
            const int kkg = kc * 2 + ks;
            uint32_t bh[2][2], bl[2][2];
            #pragma unroll
            for (int nt = 0; nt < 2; nt++) {
                uint2 v = gwfH[((nnb + nt) * 48 + kkg) * 32 + lane];
                bh[nt][0] = v.x; bh[nt][1] = v.y;
                v = gwfL[((nnb + nt) * 48 + kkg) * 32 + lane];
                bl[nt][0] = v.x; bl[nt][1] = v.y;
            }
            #pragma unroll
            for (int mt = 0; mt < 2; mt++) {
                uint32_t addr = sbase + cur * 2 * TGB +
                    (warpM * 32 + mt * 16 + (lane & 15)) * TGP +
                    (lane >> 4) * 16 + ks * 32;
                uint32_t ahf[4], alf[4];
                ldsm_x4(ahf[0], ahf[1], ahf[2], ahf[3], addr);
                ldsm_x4(alf[0], alf[1], alf[2], alf[3], addr + TGB);
                #pragma unroll
                for (int nt = 0; nt < 2; nt++) {
                    mma_bf16(c[mt][nt], ahf, bh[nt]);
                    mma_bf16(c[mt][nt], alf, bh[nt]);
                    mma_bf16(c[mt][nt], ahf, bl[nt]);
                }
            }
        }
    }

    const int gr = lane >> 2;
    const int gc = lane & 3;
    #pragma unroll
    for (int mt = 0; mt < 2; mt++)
        #pragma unroll
        for (int nt = 0; nt < 2; nt++) {
            int row0 = bm + warpM * 32 + mt * 16 + gr;
            int col  = bn + warpN * 16 + nt * 8 + gc * 2;
            *(float2*)(y + (long)row0 * DDIM + col) =
                make_float2(c[mt][nt][0], c[mt][nt][1]);
            *(float2*)(y + (long)(row0 + 8) * DDIM + col) =
                make_float2(c[mt][nt][2], c[mt][nt][3]);
        }
}

// ============================================================================
// Coalesced fragment prep (smem-staged transpose).
// ============================================================================
template <bool SPLIT>
__global__ void prep_frag(const float* __restrict__ src, int srcN, long srcStride,
                          int nnPerZ, uint2* __restrict__ dstH, uint2* __restrict__ dstL)
{
    __shared__ float tile[16][68];
    const int tid = threadIdx.x;
    const float* S = src + (long)blockIdx.z * srcStride;

    {
        int row = tid >> 4;
        int col4 = (tid & 15) * 4;
        float4 v = *(const float4*)(S + (long)(blockIdx.y * 16 + row) * srcN
                                    + blockIdx.x * 64 + col4);
        tile[row][col4 + 0] = v.x;
        tile[row][col4 + 1] = v.y;
        tile[row][col4 + 2] = v.z;
        tile[row][col4 + 3] = v.w;
    }
    __syncthreads();

    const int nn_local = tid >> 5;
    const int lane = tid & 31;
    const int n_l = nn_local * 8 + (lane >> 2);
    const int r0 = 2 * (lane & 3);
    float g0 = tile[r0][n_l],     g1 = tile[r0 + 1][n_l];
    float g2 = tile[r0 + 8][n_l], g3 = tile[r0 + 9][n_l];

    long nnG = (long)blockIdx.z * nnPerZ + blockIdx.x * 8 + nn_local;
    long idx = (nnG * 48 + blockIdx.y) * 32 + lane;

    if (SPLIT) {
        float h0 = __bfloat162float(__float2bfloat16(g0));
        float h1 = __bfloat162float(__float2bfloat16(g1));
        float h2 = __bfloat162float(__float2bfloat16(g2));
        float h3 = __bfloat162float(__float2bfloat16(g3));
        uint2 H, L;
        H.x = pack_bf16x2(h0, h1);           H.y = pack_bf16x2(h2, h3);
        L.x = pack_bf16x2(g0 - h0, g1 - h1); L.y = pack_bf16x2(g2 - h2, g3 - h3);
        dstH[idx] = H;
        dstL[idx] = L;
    } else {
        uint2 H;
        H.x = pack_bf16x2(g0, g1);
        H.y = pack_bf16x2(g2, g3);
        dstH[idx] = H;
    }
}

// ============================================================================
// Fused edge-MLP v2: 512 threads, 1 CTA/SM, PERSISTENT A (full 128x768 bf16
// in SMEM, built once), 16 warps as 2M x 8N covering all 384 N columns in a
// single barrier-free K sweep. One CTA per (b,i).
// ============================================================================
#define APITCH 144
#define ABUF   18432
#define SM_A     0                        // 12 chunks: 221184
#define SM_HIB   221184                   // 768 fp32
#define SM_B2    224256
#define SM_W3    225792
#define SM_SCAL  227328
#define SM_RED   227840
#define SM_TOTAL 227904

__global__ __launch_bounds__(512, 1)
void edge_mma_kernel(const float* __restrict__ hi, const __nv_bfloat16* __restrict__ hj2,
                     const float* __restrict__ adj, const float* __restrict__ b1,
                     const uint2* __restrict__ bfrag, const float* __restrict__ b2,
                     const float* __restrict__ w3, const float* __restrict__ b3p,
                     float* __restrict__ a_out, float* __restrict__ denom_out)
{
    extern __shared__ char smem[];
    const uint32_t sbase = smem_to_u32(smem);
    const int tid  = threadIdx.x;
    const int lane = tid & 31;
    const int wid  = tid >> 5;          // 0..15
    const int warpM = wid >> 3;         // 0..1  (64 rows)
    const int warpN = wid & 7;          // 0..7  (48 cols)
    const int bi = blockIdx.x;
    const int b  = bi >> 7;
    const int i  = bi & 127;

    float* hib  = (float*)(smem + SM_HIB);
    float* b2s  = (float*)(smem + SM_B2);
    float* w3s  = (float*)(smem + SM_W3);
    float* scal = (float*)(smem + SM_SCAL);
    float* red  = (float*)(smem + SM_RED);

    for (int k = tid; k < DDIM; k += 512) hib[k] = hi[(long)bi * DDIM + k] + b1[k];
    if (tid < 384) { b2s[tid] = b2[tid]; w3s[tid] = w3[tid]; }
    if (tid < 128) scal[tid] = 0.f;
    __syncthreads();

    // ---------------- build persistent A (once): 12 chunks ----------------
    {
        const int aj  = tid >> 2;       // row 0..127
        const int seg = tid & 3;        // 16 bf16 per chunk
        const uint4*  hjs = (const uint4*)(hj2 + ((long)b * LSEQ + aj) * DDIM) + seg * 2;
        const float4* hbs = (const float4*)hib + seg * 4;
        char* arow = smem + SM_A + aj * APITCH + seg * 32;
        #pragma unroll
        for (int kc = 0; kc < 12; kc++) {
            #pragma unroll
            for (int s = 0; s < 2; s++) {
                uint4 v = hjs[kc * 8 + s];
                float4 f0 = hbs[kc * 16 + s * 2];
                float4 f1 = hbs[kc * 16 + s * 2 + 1];
                const __nv_bfloat162* p = (const __nv_bfloat162*)&v;
                float2 a0 = __bfloat1622float2(p[0]);
                float2 a1 = __bfloat1622float2(p[1]);
                float2 a2 = __bfloat1622float2(p[2]);
                float2 a3 = __bfloat1622float2(p[3]);
                uint4 o;
                o.x = pack_bf16x2(fmaxf(a0.x + f0.x, 0.f), fmaxf(a0.y + f0.y, 0.f));
                o.y = pack_bf16x2(fmaxf(a1.x + f0.z, 0.f), fmaxf(a1.y + f0.w, 0.f));
                o.z = pack_bf16x2(fmaxf(a2.x + f1.x, 0.f), fmaxf(a2.y + f1.y, 0.f));
                o.w = pack_bf16x2(fmaxf(a3.x + f1.z, 0.f), fmaxf(a3.y + f1.w, 0.f));
                *(uint4*)(arow + kc * ABUF + s * 16) = o;
            }
        }
    }
    __syncthreads();

    // ---------------- barrier-free mainloop over full K, full N ----------------
    float c[4][6][4];
    #pragma unroll
    for (int mt = 0; mt < 4; mt++)
        #pragma unroll
        for (int nt = 0; nt < 6; nt++)
            #pragma unroll
            for (int q = 0; q < 4; q++) c[mt][nt][q] = 0.f;

    const uint2* bb = bfrag + ((long)(warpN * 6) * 48) * 32 + lane;
    const uint32_t a_lane = sbase + SM_A +
        (warpM * 64 + (lane & 15)) * APITCH + (lane >> 4) * 16;

    for (int kc = 0; kc < 12; kc++) {
        const uint32_t abase_k = a_lane + kc * ABUF;
        #pragma unroll
        for (int ks = 0; ks < 4; ks++) {
            uint32_t bfr[6][2];
            #pragma unroll
            for (int nt = 0; nt < 6; nt++) {
                uint2 v = bb[((long)nt * 48 + kc * 4 + ks) * 32];
                bfr[nt][0] = v.x;
                bfr[nt][1] = v.y;
            }
            #pragma unroll
            for (int mt = 0; mt < 4; mt++) {
                uint32_t afr[4];
                ldsm_x4(afr[0], afr[1], afr[2], afr[3],
                        abase_k + mt * 16 * APITCH + ks * 32);
                #pragma unroll
                for (int nt = 0; nt < 6; nt++)
                    mma_bf16(c[mt][nt], afr, bfr[nt]);
            }
        }
    }

    // ---------------- epilogue: relu(+b2) * w3, reduce into scal ----------------
    {
        const int qr = lane >> 2;
        const int qc = lane & 3;
        #pragma unroll
        for (int mt = 0; mt < 4; mt++) {
            float p0 = 0.f, p1 = 0.f;
            #pragma unroll
            for (int nt = 0; nt < 6; nt++) {
                int n0 = warpN * 48 + nt * 8 + qc * 2;
                float bw0 = b2s[n0], bw1 = b2s[n0 + 1];
                float ww0 = w3s[n0], ww1 = w3s[n0 + 1];
                p0 += fmaxf(c[mt][nt][0] + bw0, 0.f) * ww0
                    + fmaxf(c[mt][nt][1] + bw1, 0.f) * ww1;
                p1 += fmaxf(c[mt][nt][2] + bw0, 0.f) * ww0
                    + fmaxf(c[mt][nt][3] + bw1, 0.f) * ww1;
            }
            p0 += __shfl_xor_sync(0xffffffffu, p0, 1);
            p0 += __shfl_xor_sync(0xffffffffu, p0, 2);
            p1 += __shfl_xor_sync(0xffffffffu, p1, 1);
            p1 += __shfl_xor_sync(0xffffffffu, p1, 2);
            if (qc == 0) {
                atomicAdd(&scal[warpM * 64 + mt * 16 + qr], p0);
                atomicAdd(&scal[warpM * 64 + mt * 16 + qr + 8], p1);
            }
        }
    }
    __syncthreads();

    // ---- sigmoid -> adj mix -> +eye -> softmax -> denom ----
    if (tid < 128) {
        float x  = scal[tid] + b3p[0];
        float ew = 1.f / (1.f + expf(-x));
        scal[tid] = adj[(long)bi * 128 + tid] * ew + (tid == i ? 1.f : 0.f);
    }
    __syncthreads();
    if (tid < 32) {
        float m = fmaxf(fmaxf(scal[tid], scal[tid + 32]),
                        fmaxf(scal[tid + 64], scal[tid + 96]));
        for (int sh = 16; sh; sh >>= 1) m = fmaxf(m, __shfl_xor_sync(0xffffffffu, m, sh));
        if (tid == 0) red[0] = m;
    }
    __syncthreads();
    if (tid < 128) scal[tid] = expf(scal[tid] - red[0]);
    __syncthreads();
    if (tid < 32) {
        float s = scal[tid] + scal[tid + 32] + scal[tid + 64] + scal[tid + 96];
        for (int sh = 16; sh; sh >>= 1) s += __shfl_xor_sync(0xffffffffu, s, sh);
        if (tid == 0) red[1] = s;
    }
    __syncthreads();
    if (tid < 128) {
        float p = scal[tid] / red[1];
        a_out[(long)bi * 128 + tid] = p + (tid == i ? 1.f : 0.f);
        scal[tid] = p;
    }
    __syncthreads();
    if (tid < 32) {
        float s = scal[tid] + scal[tid + 32] + scal[tid + 64] + scal[tid + 96];
        for (int sh = 16; sh; sh >>= 1) s += __shfl_xor_sync(0xffffffffu, s, sh);
        if (tid == 0) denom_out[bi] = 1.f + s;
    }
}

// ---------------- fused bias + denom + relu + LayerNorm ----------------------
__global__ __launch_bounds__(256)
void ln_kernel(const float* __restrict__ y, const float* __restrict__ gb,
               const float* __restrict__ lng, const float* __restrict__ lnb,
               const float* __restrict__ denom, float* __restrict__ outp)
{
    const int row = blockIdx.x;
    const int tid = threadIdx.x;
    const float inv = 1.f / denom[row];
    const float* yr = y + (long)row * DDIM;

    float v[3];
    float s = 0.f, sq = 0.f;
    #pragma unroll
    for (int p = 0; p < 3; p++) {
        int n = tid + p * 256;
        float x = fmaxf((yr[n] + 2.f * gb[n]) * inv, 0.f);
        v[p] = x; s += x; sq += x * x;
    }
    __shared__ float rs[8], rq[8], mm[2];
    for (int sh = 16; sh; sh >>= 1) {
        s  += __shfl_xor_sync(0xffffffffu, s,  sh);
        sq += __shfl_xor_sync(0xffffffffu, sq, sh);
    }
    if ((tid & 31) == 0) { rs[tid >> 5] = s; rq[tid >> 5] = sq; }
    __syncthreads();
    if (tid == 0) {
        float S = 0.f, Q = 0.f;
        #pragma unroll
        for (int q = 0; q < 8; q++) { S += rs[q]; Q += rq[q]; }
        float mean = S / (float)DDIM;
        float var  = Q / (float)DDIM - mean * mean;
        mm[0] = mean;
        mm[1] = rsqrtf(var + 1e-5f);
    }
    __syncthreads();
    const float mean = mm[0], rstd = mm[1];
    float* orow = outp + (long)row * DDIM;
    #pragma unroll
    for (int p = 0; p < 3; p++) {
        int n = tid + p * 256;
        orow[n] = (v[p] - mean) * rstd * lng[n] + lnb[n];
    }
}

// ---------------- zero mask tail ---------------------------------------------
__global__ void zero_tail_kernel(float* __restrict__ dst, int start, int total)
{
    int idx = start + blockIdx.x * 256 + threadIdx.x;
    if (idx < total) dst[idx] = 0.f;
}

// ---------------- launch ------------------------------------------------------
extern "C" void kernel_launch(void* const* d_in, const int* in_sizes, int n_in,
                              void* d_out, int out_size)
{
    const float* adj    = (const float*)d_in[0];
    const float* inputs = (const float*)d_in[1];
    const float* w1     = (const float*)d_in[2];
    const float* b1     = (const float*)d_in[3];
    const float* w2     = (const float*)d_in[4];
    const float* b2     = (const float*)d_in[5];
    const float* w3     = (const float*)d_in[6];
    const float* b3     = (const float*)d_in[7];
    const float* gw     = (const float*)d_in[8];
    const float* gb     = (const float*)d_in[9];
    const float* lng    = (const float*)d_in[10];
    const float* lnb    = (const float*)d_in[11];

    float *hi, *a, *denom, *y, *buf;
    __nv_bfloat16 *hj2, *tH, *tL;
    uint2 *bfrag, *gwfH, *gwfL;
    cudaGetSymbolAddress((void**)&hi,    g_hi);
    cudaGetSymbolAddress((void**)&a,     g_a);
    cudaGetSymbolAddress((void**)&denom, g_denom);
    cudaGetSymbolAddress((void**)&y,     g_y);
    cudaGetSymbolAddress((void**)&buf,   g_buf);
    cudaGetSymbolAddress((void**)&hj2,   g_hj2);
    cudaGetSymbolAddress((void**)&tH,    g_tH);
    cudaGetSymbolAddress((void**)&tL,    g_tL);
    cudaGetSymbolAddress((void**)&bfrag, g_bfrag);
    cudaGetSymbolAddress((void**)&gwfH,  g_gwfH);
    cudaGetSymbolAddress((void**)&gwfL,  g_gwfL);

    cudaFuncSetAttribute(edge_mma_kernel,
                         cudaFuncAttributeMaxDynamicSharedMemorySize, SM_TOTAL);

    dim3 blk(256);

    // w2 fragments first (edge needs them), then hi/hj GEMM, then gw fragments.
    prep_frag<false><<<dim3(6, 48, 1), blk>>>(w2, 384, 0L, 0, bfrag, nullptr);

    // hi = X @ w1[:768] (fp32), hj = X @ w1[768:] (bf16, direct) — ONE 192-CTA launch
    gemm_tf32<128, false, 3><<<dim3(12, 8, 2), blk>>>(
        inputs, w1, hi, nullptr, hj2, nullptr,
        ROWS, DDIM, DDIM, 0L, (long)DDIM * DDIM, 0L);

    prep_frag<true><<<dim3(12, 48, 3), blk>>>(gw, DDIM, (long)DDIM * DDIM, 96,
                                              gwfH, gwfL);

    // fused edge MLP v2 (persistent A, 512 threads) -> a (= softmax + I), denom
    edge_mma_kernel<<<1024, 512, SM_TOTAL>>>(hi, hj2, adj, b1, bfrag, b2, w3, b3,
                                             a, denom);

    const float* cur = inputs;
    for (int li = 0; li < 3; li++) {
        // t = (a + I) @ cur  (3xTF32 exact; epilogue emits bf16 hi/lo); 192 CTAs
        gemm_tf32<64, true, 1><<<dim3(12, 2, NBATCH), blk>>>(
            a, cur, nullptr, nullptr, tH, tL,
            LSEQ, DDIM, LSEQ,
            (long)LSEQ * LSEQ, (long)LSEQ * DDIM, (long)LSEQ * DDIM);
        // y = t @ gw[li]  (split-bf16 exact); 192 CTAs
        gemm_tgw<<<dim3(12, 16), blk>>>(tH, tL, gwfH, gwfL, li, y);
        float* nxt = (li == 2) ? (float*)d_out
                               : buf + (long)(li & 1) * ROWS * DDIM;
        ln_kernel<<<1024, blk>>>(y, gb + li * DDIM, lng + li * DDIM, lnb + li * DDIM,
                                 denom, nxt);
        cur = nxt;
    }

    int tail = out_size - ROWS * DDIM;
    if (tail > 0)
        zero_tail_kernel<<<(tail + 255) / 256, blk>>>((float*)d_out, ROWS * DDIM, out_size);
}